// round 13
// baseline (speedup 1.0000x reference)
#include <cuda_runtime.h>
#include <cuda_bf16.h>
#include <stdint.h>
#include <cstdint>
#include <math.h>

#define Bb 2
#define C 256
#define Nn 8192
#define G 32
#define CPG 8
#define TQ 64
#define TK 32
#define NT (Nn / TK)   // 256 key tiles

// Scratch (no allocations allowed)
__device__ __nv_bfloat16 d_q[(size_t)Bb * Nn * C];     // [b][n][c]
__device__ __nv_bfloat16 d_k[(size_t)Bb * Nn * C];     // [b][n][c]
__device__ __nv_bfloat16 d_v[(size_t)Bb * C * Nn];     // [b][c][n]
__device__ __nv_bfloat16 d_attno[(size_t)Bb * Nn * C]; // [b][n][c] bf16
__device__ float d_ga[Bb * C];
__device__ float d_gb[Bb * C];

// ---------------------------------------------------------------------------
__device__ __forceinline__ uint32_t smem_u32(const void* p) {
    uint32_t a;
    asm("{ .reg .u64 t; cvta.to.shared.u64 t, %1; cvt.u32.u64 %0, t; }" : "=r"(a) : "l"(p));
    return a;
}
__device__ __forceinline__ void ldsm4(uint32_t a, uint32_t& d0, uint32_t& d1,
                                      uint32_t& d2, uint32_t& d3) {
    asm volatile("ldmatrix.sync.aligned.m8n8.x4.shared.b16 {%0,%1,%2,%3}, [%4];"
                 : "=r"(d0), "=r"(d1), "=r"(d2), "=r"(d3) : "r"(a));
}
__device__ __forceinline__ void mma_bf16(float& c0, float& c1, float& c2, float& c3,
                                         uint32_t a0, uint32_t a1, uint32_t a2, uint32_t a3,
                                         uint32_t b0, uint32_t b1) {
    asm volatile("mma.sync.aligned.m16n8k16.row.col.f32.bf16.bf16.f32 "
                 "{%0,%1,%2,%3}, {%4,%5,%6,%7}, {%8,%9}, {%0,%1,%2,%3};"
                 : "+f"(c0), "+f"(c1), "+f"(c2), "+f"(c3)
                 : "r"(a0), "r"(a1), "r"(a2), "r"(a3), "r"(b0), "r"(b1));
}
__device__ __forceinline__ void cpa16(uint32_t dst, const void* src) {
    asm volatile("cp.async.cg.shared.global [%0], [%1], 16;" :: "r"(dst), "l"(src) : "memory");
}
#define CP_COMMIT() asm volatile("cp.async.commit_group;" ::: "memory")
#define CP_WAIT(n)  asm volatile("cp.async.wait_group %0;" :: "n"(n) : "memory")

__device__ __forceinline__ uint32_t packbf2(float a, float b) {
    __nv_bfloat162 h = __float22bfloat162_rn(make_float2(a, b));
    return *(uint32_t*)&h;
}
__device__ __forceinline__ uint32_t packu16(uint32_t lo, uint32_t hi) {
    return (lo & 0xffffu) | (hi << 16);
}

// ---------------------------------------------------------------------------
// Kernel 1: GroupNorm statistics -> per-channel affine params
// ---------------------------------------------------------------------------
__global__ __launch_bounds__(256) void gn_stats(const float* __restrict__ x,
                                                const float* __restrict__ nw,
                                                const float* __restrict__ nb) {
    int b = blockIdx.x >> 5, g = blockIdx.x & 31;
    const float4* p = (const float4*)(x + ((size_t)b * C + (size_t)g * CPG) * Nn);
    float s = 0.f, ss = 0.f;
    const int total4 = CPG * Nn / 4;
    for (int i = threadIdx.x; i < total4; i += 256) {
        float4 v4 = p[i];
        s += v4.x + v4.y + v4.z + v4.w;
        ss += v4.x * v4.x + v4.y * v4.y + v4.z * v4.z + v4.w * v4.w;
    }
    for (int off = 16; off; off >>= 1) {
        s += __shfl_xor_sync(0xffffffffu, s, off);
        ss += __shfl_xor_sync(0xffffffffu, ss, off);
    }
    __shared__ float rsm[8], rssm[8];
    int w = threadIdx.x >> 5, ln = threadIdx.x & 31;
    if (ln == 0) { rsm[w] = s; rssm[w] = ss; }
    __syncthreads();
    if (threadIdx.x < 8) {
        s = rsm[threadIdx.x]; ss = rssm[threadIdx.x];
        for (int off = 4; off; off >>= 1) {
            s += __shfl_xor_sync(0xffu, s, off);
            ss += __shfl_xor_sync(0xffu, ss, off);
        }
        float mean = s * (1.f / 65536.f);
        float var = ss * (1.f / 65536.f) - mean * mean;
        float rstd = rsqrtf(var + 1e-5f);
        int c = g * CPG + threadIdx.x;
        float wv = nw[c];
        d_ga[b * C + c] = rstd * wv;
        d_gb[b * C + c] = nb[c] - mean * rstd * wv;
    }
}

// ---------------------------------------------------------------------------
// Kernel 2: QKV GEMM tensor cores, o-tile 256 (y: 0=q, 1=k, 2=v), fused norm.
// ---------------------------------------------------------------------------
__global__ __launch_bounds__(256) void qkv_mma(const float* __restrict__ x,
                                               const float* __restrict__ W,
                                               const float* __restrict__ bias) {
    __shared__ __align__(16) char ws_[256 * 80];
    __shared__ __align__(16) char un_[18432];
    const uint32_t sws = smem_u32(ws_), sun = smem_u32(un_);
    const uint32_t shs = sun + 8704;
    const int b = blockIdx.z, o0 = blockIdx.y * 256, n0 = blockIdx.x * 64;
    const int t = threadIdx.x, w = t >> 5, lane = t & 31;
    const float* xb = x + (size_t)b * C * Nn;

    const int qb = w * 16;
    const uint32_t aW0 = sws + (qb + (lane & 15)) * 80 + ((lane >> 4) << 4);
    const uint32_t aW1 = aW0 + 128 * 80;
    const uint32_t bHrow = (lane & 7) + ((lane >> 4) << 3);
    const uint32_t bHcol = (lane & 8) ? 16u : 0u;

    float acc[2][4][2][4] = {};

    for (int k0 = 0; k0 < C; k0 += 32) {
#pragma unroll
        for (int i = 0; i < 8; i++) {
            int idx = t + i * 256, oo = idx >> 3, kg = idx & 7;
            float4 v4 = *(const float4*)&W[(size_t)(o0 + oo) * C + k0 + kg * 4];
            uint32_t* dp = (uint32_t*)(ws_ + oo * 80 + kg * 8);
            dp[0] = packbf2(v4.x, v4.y);
            dp[1] = packbf2(v4.z, v4.w);
        }
#pragma unroll
        for (int i = 0; i < 2; i++) {
            int idx = t + i * 256, cc = idx >> 4, n4 = idx & 15;
            int c = k0 + cc;
            float av = d_ga[b * C + c], bv = d_gb[b * C + c];
            float4 v4 = *(const float4*)&xb[(size_t)c * Nn + n0 + n4 * 4];
            *(float4*)(un_ + (cc * 68 + n4 * 4) * 4) =
                make_float4(v4.x * av + bv, v4.y * av + bv, v4.z * av + bv, v4.w * av + bv);
        }
        __syncthreads();
        {
            int n = t & 63, kg = t >> 6;
            float f[8];
#pragma unroll
            for (int j = 0; j < 8; j++)
                f[j] = *(float*)(un_ + ((kg * 8 + j) * 68 + n) * 4);
            uint4 u;
            u.x = packbf2(f[0], f[1]); u.y = packbf2(f[2], f[3]);
            u.z = packbf2(f[4], f[5]); u.w = packbf2(f[6], f[7]);
            *(uint4*)(un_ + 8704 + n * 80 + kg * 16) = u;
        }
        __syncthreads();
#pragma unroll
        for (int kt = 0; kt < 2; kt++) {
            uint32_t a0, a1, a2, a3, c0, c1, c2, c3;
            ldsm4(aW0 + kt * 32, a0, a1, a2, a3);
            ldsm4(aW1 + kt * 32, c0, c1, c2, c3);
#pragma unroll
            for (int nbk = 0; nbk < 4; nbk++) {
                uint32_t b0, b1, b2, b3;
                ldsm4(shs + (nbk * 16 + bHrow) * 80 + kt * 32 + bHcol, b0, b1, b2, b3);
                mma_bf16(acc[0][nbk][0][0], acc[0][nbk][0][1], acc[0][nbk][0][2], acc[0][nbk][0][3],
                         a0, a1, a2, a3, b0, b1);
                mma_bf16(acc[0][nbk][1][0], acc[0][nbk][1][1], acc[0][nbk][1][2], acc[0][nbk][1][3],
                         a0, a1, a2, a3, b2, b3);
                mma_bf16(acc[1][nbk][0][0], acc[1][nbk][0][1], acc[1][nbk][0][2], acc[1][nbk][0][3],
                         c0, c1, c2, c3, b0, b1);
                mma_bf16(acc[1][nbk][1][0], acc[1][nbk][1][1], acc[1][nbk][1][2], acc[1][nbk][1][3],
                         c0, c1, c2, c3, b2, b3);
            }
        }
        __syncthreads();
    }

    const int r = qb + (lane >> 2);

    if (blockIdx.y < 2) {
        __nv_bfloat16* dst = ((blockIdx.y == 0) ? d_q : d_k) + (size_t)b * Nn * C;
#pragma unroll
        for (int h = 0; h < 2; h++) {
            float bi0 = bias[o0 + h * 128 + r], bi1 = bias[o0 + h * 128 + r + 8];
#pragma unroll
            for (int nbk = 0; nbk < 4; nbk++)
#pragma unroll
                for (int nn = 0; nn < 2; nn++) {
                    int n = nbk * 16 + nn * 8 + 2 * (lane & 3);
                    *(uint32_t*)(un_ + r * 144 + n * 2) =
                        packbf2(acc[h][nbk][nn][0] + bi0, acc[h][nbk][nn][1] + bi0);
                    *(uint32_t*)(un_ + (r + 8) * 144 + n * 2) =
                        packbf2(acc[h][nbk][nn][2] + bi1, acc[h][nbk][nn][3] + bi1);
                }
            __syncthreads();
#pragma unroll
            for (int i = 0; i < 4; i++) {
                int idx = t + i * 256, n = idx & 63, og = idx >> 6;
                uint32_t hh[8];
#pragma unroll
                for (int j = 0; j < 8; j++)
                    hh[j] = *(uint16_t*)(un_ + (og * 8 + j) * 144 + n * 2);
                uint4 u;
                u.x = packu16(hh[0], hh[1]); u.y = packu16(hh[2], hh[3]);
                u.z = packu16(hh[4], hh[5]); u.w = packu16(hh[6], hh[7]);
                *(uint4*)&dst[(size_t)(n0 + n) * C + h * 128 + og * 8] = u;
            }
            __syncthreads();
        }
    } else {
        __nv_bfloat16* dst = d_v + (size_t)b * C * Nn;
#pragma unroll
        for (int h = 0; h < 2; h++) {
            int ch = h * 128 + r;
            float bi0 = bias[o0 + ch], bi1 = bias[o0 + ch + 8];
#pragma unroll
            for (int nbk = 0; nbk < 4; nbk++)
#pragma unroll
                for (int nn = 0; nn < 2; nn++) {
                    int n = n0 + nbk * 16 + nn * 8 + 2 * (lane & 3);
                    *(uint32_t*)&dst[(size_t)ch * Nn + n] =
                        packbf2(acc[h][nbk][nn][0] + bi0, acc[h][nbk][nn][1] + bi0);
                    *(uint32_t*)&dst[(size_t)(ch + 8) * Nn + n] =
                        packbf2(acc[h][nbk][nn][2] + bi1, acc[h][nbk][nn][3] + bi1);
                }
        }
    }
}

// ---------------------------------------------------------------------------
// Kernel 3: bf16 flash attention, FA2 register-P. TQ=64, TK=32,
// 128 threads (4 warps x 16 q-rows), double buffer, 2 CTAs/SM.
// ---------------------------------------------------------------------------
#define QS_OFF  0u
#define KS0_OFF 33792u
#define KS1_OFF 50688u
#define VS0_OFF 67584u
#define VS1_OFF 88064u
#define SMEM_FLASH 108544
#define NTHR 128

__global__ __launch_bounds__(NTHR, 2) void flash_mma() {
    extern __shared__ __align__(16) char sm[];
    const uint32_t sb = smem_u32(sm);
    const int t = threadIdx.x, w = t >> 5, lane = t & 31;
    const int b = blockIdx.y, q0 = blockIdx.x * TQ;
    const __nv_bfloat16* qg = d_q + (size_t)b * Nn * C;
    const __nv_bfloat16* kg = d_k + (size_t)b * Nn * C;
    const __nv_bfloat16* vg = d_v + (size_t)b * C * Nn;

    // stage Q: 64 rows x 512B (stride 528)
#pragma unroll
    for (int i = 0; i < 16; i++) {
        int g = t + i * NTHR, row = g >> 5, ck = g & 31;
        cpa16(sb + QS_OFF + row * 528 + ck * 16, qg + (size_t)(q0 + row) * C + ck * 8);
    }
    // tile 0: K 32x528, V 256x80
#pragma unroll
    for (int i = 0; i < 8; i++) {
        int g = t + i * NTHR, row = g >> 5, ck = g & 31;
        cpa16(sb + KS0_OFF + row * 528 + ck * 16, kg + (size_t)row * C + ck * 8);
    }
#pragma unroll
    for (int i = 0; i < 8; i++) {
        int g = t + i * NTHR, ch = g >> 2, ck = g & 3;
        cpa16(sb + VS0_OFF + ch * 80 + ck * 16, vg + (size_t)ch * Nn + ck * 8);
    }
    CP_COMMIT();

    float O[32][4];
#pragma unroll
    for (int m = 0; m < 32; m++)
#pragma unroll
        for (int c = 0; c < 4; c++) O[m][c] = 0.f;
    float l0 = 0.f, l1 = 0.f;

    const int qb = w * 16;
    const uint32_t aQ = sb + QS_OFF + (qb + (lane & 15)) * 528 + ((lane >> 4) * 8) * 2;
    const uint32_t bKrow = (lane & 7) + ((lane >> 4) << 3);
    const uint32_t bKcol = (lane & 8) ? 16u : 0u;

    for (int tile = 0; tile < NT; tile++) {
        const uint32_t kcur = sb + ((tile & 1) ? KS1_OFF : KS0_OFF);
        const uint32_t vcur = sb + ((tile & 1) ? VS1_OFF : VS0_OFF);
        if (tile + 1 < NT) {
            const uint32_t kn = sb + (((tile + 1) & 1) ? KS1_OFF : KS0_OFF);
            const uint32_t vn = sb + (((tile + 1) & 1) ? VS1_OFF : VS0_OFF);
            const int kk1 = (tile + 1) * TK;
#pragma unroll
            for (int i = 0; i < 8; i++) {
                int g = t + i * NTHR, row = g >> 5, ck = g & 31;
                cpa16(kn + row * 528 + ck * 16, kg + (size_t)(kk1 + row) * C + ck * 8);
            }
#pragma unroll
            for (int i = 0; i < 8; i++) {
                int g = t + i * NTHR, ch = g >> 2, ck = g & 3;
                cpa16(vn + ch * 80 + ck * 16, vg + (size_t)ch * Nn + kk1 + ck * 8);
            }
            CP_COMMIT();
            CP_WAIT(1);
        } else {
            CP_WAIT(0);
        }
        __syncthreads();

        // ---- S = Q K^T (16 q x 32 keys per warp) ----
        float S[4][4];
#pragma unroll
        for (int nt = 0; nt < 4; nt++)
#pragma unroll
            for (int c = 0; c < 4; c++) S[nt][c] = 0.f;
#pragma unroll
        for (int kt = 0; kt < 16; kt++) {
            uint32_t a0, a1, a2, a3;
            ldsm4(aQ + kt * 32, a0, a1, a2, a3);
#pragma unroll
            for (int kb = 0; kb < 2; kb++) {
                uint32_t b0, b1, b2, b3;
                ldsm4(kcur + (kb * 16 + bKrow) * 528 + kt * 32 + bKcol, b0, b1, b2, b3);
                mma_bf16(S[2 * kb][0], S[2 * kb][1], S[2 * kb][2], S[2 * kb][3],
                         a0, a1, a2, a3, b0, b1);
                mma_bf16(S[2 * kb + 1][0], S[2 * kb + 1][1], S[2 * kb + 1][2], S[2 * kb + 1][3],
                         a0, a1, a2, a3, b2, b3);
            }
        }

        // ---- softmax (no max) -> A-fragments in registers ----
        uint32_t aP[2][4];
#pragma unroll
        for (int ka = 0; ka < 2; ka++) {
            float p00 = __expf(S[2 * ka][0] * 0.0625f);
            float p01 = __expf(S[2 * ka][1] * 0.0625f);
            float p02 = __expf(S[2 * ka][2] * 0.0625f);
            float p03 = __expf(S[2 * ka][3] * 0.0625f);
            float p10 = __expf(S[2 * ka + 1][0] * 0.0625f);
            float p11 = __expf(S[2 * ka + 1][1] * 0.0625f);
            float p12 = __expf(S[2 * ka + 1][2] * 0.0625f);
            float p13 = __expf(S[2 * ka + 1][3] * 0.0625f);
            l0 += (p00 + p01) + (p10 + p11);
            l1 += (p02 + p03) + (p12 + p13);
            aP[ka][0] = packbf2(p00, p01);
            aP[ka][1] = packbf2(p02, p03);
            aP[ka][2] = packbf2(p10, p11);
            aP[ka][3] = packbf2(p12, p13);
        }

        // ---- O += P V^T (V as B operand) ----
#pragma unroll
        for (int cb = 0; cb < 16; cb++) {
            uint32_t vbase = vcur + (cb * 16 + bKrow) * 80 + bKcol;
#pragma unroll
            for (int ka = 0; ka < 2; ka++) {
                uint32_t b0, b1, b2, b3;
                ldsm4(vbase + ka * 32, b0, b1, b2, b3);
                mma_bf16(O[2 * cb][0], O[2 * cb][1], O[2 * cb][2], O[2 * cb][3],
                         aP[ka][0], aP[ka][1], aP[ka][2], aP[ka][3], b0, b1);
                mma_bf16(O[2 * cb + 1][0], O[2 * cb + 1][1], O[2 * cb + 1][2], O[2 * cb + 1][3],
                         aP[ka][0], aP[ka][1], aP[ka][2], aP[ka][3], b2, b3);
            }
        }
        __syncthreads();
    }

    // ---- reduce l across quad, normalize, store [n][c] ----
    l0 += __shfl_xor_sync(0xffffffffu, l0, 1);
    l0 += __shfl_xor_sync(0xffffffffu, l0, 2);
    l1 += __shfl_xor_sync(0xffffffffu, l1, 1);
    l1 += __shfl_xor_sync(0xffffffffu, l1, 2);
    float inv0 = 1.f / l0, inv1 = 1.f / l1;
    __nv_bfloat16* ao = d_attno + (size_t)b * Nn * C;
    int nr = q0 + qb + (lane >> 2);
#pragma unroll
    for (int ob = 0; ob < 32; ob++) {
        int cc = (ob >> 1) * 16 + (ob & 1) * 8 + 2 * (lane & 3);
        *(uint32_t*)&ao[(size_t)nr * C + cc] = packbf2(O[ob][0] * inv0, O[ob][1] * inv0);
        *(uint32_t*)&ao[(size_t)(nr + 8) * C + cc] = packbf2(O[ob][2] * inv1, O[ob][3] * inv1);
    }
}

// ---------------------------------------------------------------------------
// Kernel 4: projection GEMM + bias + residual (attno [n][c] native B layout)
// ---------------------------------------------------------------------------
__global__ __launch_bounds__(256) void proj_mma(const float* __restrict__ x,
                                                const float* __restrict__ W,
                                                const float* __restrict__ bias,
                                                float* __restrict__ out) {
    __shared__ __align__(16) char ws_[128 * 80];
    __shared__ __align__(16) char hs_[64 * 80];
    const uint32_t sws = smem_u32(ws_), shs = smem_u32(hs_);
    const int b = blockIdx.z, o0 = blockIdx.y * 128, n0 = blockIdx.x * 64;
    const int t = threadIdx.x, w = t >> 5, lane = t & 31;
    const __nv_bfloat16* ab = d_attno + (size_t)b * Nn * C;

    const int qb = w * 16;
    const uint32_t aW = sws + (qb + (lane & 15)) * 80 + ((lane >> 4) << 4);
    const uint32_t bHrow = (lane & 7) + ((lane >> 4) << 3);
    const uint32_t bHcol = (lane & 8) ? 16u : 0u;

    float acc[4][2][4] = {};

    for (int k0 = 0; k0 < C; k0 += 32) {
        {
            int nn = t >> 2, ck = t & 3;
            cpa16(shs + nn * 80 + ck * 16, ab + (size_t)(n0 + nn) * C + k0 + ck * 8);
        }
        CP_COMMIT();
#pragma unroll
        for (int i = 0; i < 4; i++) {
            int idx = t + i * 256, oo = idx >> 3, kg = idx & 7;
            float4 v4 = *(const float4*)&W[(size_t)(o0 + oo) * C + k0 + kg * 4];
            uint32_t* dp = (uint32_t*)(ws_ + oo * 80 + kg * 8);
            dp[0] = packbf2(v4.x, v4.y);
            dp[1] = packbf2(v4.z, v4.w);
        }
        CP_WAIT(0);
        __syncthreads();
#pragma unroll
        for (int kt = 0; kt < 2; kt++) {
            uint32_t a0, a1, a2, a3;
            ldsm4(aW + kt * 32, a0, a1, a2, a3);
#pragma unroll
            for (int nbk = 0; nbk < 4; nbk++) {
                uint32_t b0, b1, b2, b3;
                ldsm4(shs + (nbk * 16 + bHrow) * 80 + kt * 32 + bHcol, b0, b1, b2, b3);
                mma_bf16(acc[nbk][0][0], acc[nbk][0][1], acc[nbk][0][2], acc[nbk][0][3],
                         a0, a1, a2, a3, b0, b1);
                mma_bf16(acc[nbk][1][0], acc[nbk][1][1], acc[nbk][1][2], acc[nbk][1][3],
                         a0, a1, a2, a3, b2, b3);
            }
        }
        __syncthreads();
    }

    const int r = qb + (lane >> 2);
    const float bi0 = bias[o0 + r], bi1 = bias[o0 + r + 8];
    size_t row0 = ((size_t)b * C + o0 + r) * Nn + n0;
    size_t row1 = ((size_t)b * C + o0 + r + 8) * Nn + n0;
#pragma unroll
    for (int nbk = 0; nbk < 4; nbk++)
#pragma unroll
        for (int nn = 0; nn < 2; nn++) {
            int n = nbk * 16 + nn * 8 + 2 * (lane & 3);
            float2 x0 = *(const float2*)&x[row0 + n];
            float2 x1 = *(const float2*)&x[row1 + n];
            *(float2*)&out[row0 + n] = make_float2(x0.x + acc[nbk][nn][0] + bi0,
                                                   x0.y + acc[nbk][nn][1] + bi0);
            *(float2*)&out[row1 + n] = make_float2(x1.x + acc[nbk][nn][2] + bi1,
                                                   x1.y + acc[nbk][nn][3] + bi1);
        }
}

// ---------------------------------------------------------------------------
extern "C" void kernel_launch(void* const* d_in, const int* in_sizes, int n_in,
                              void* d_out, int out_size) {
    const float* x  = (const float*)d_in[0];
    const float* nw = (const float*)d_in[1];
    const float* nb = (const float*)d_in[2];
    const float* qw = (const float*)d_in[3];
    const float* qb = (const float*)d_in[4];
    const float* pw = (const float*)d_in[5];
    const float* pb = (const float*)d_in[6];
    float* out = (float*)d_out;

    cudaFuncSetAttribute(flash_mma, cudaFuncAttributeMaxDynamicSharedMemorySize,
                         SMEM_FLASH);

    gn_stats<<<Bb * G, 256>>>(x, nw, nb);
    qkv_mma<<<dim3(Nn / 64, 3, Bb), 256>>>(x, qw, qb);
    flash_mma<<<dim3(Nn / TQ, Bb), NTHR, SMEM_FLASH>>>();
    proj_mma<<<dim3(Nn / 64, C / 128, Bb), 256>>>(x, pw, pb, out);
}

// round 15
// speedup vs baseline: 1.1529x; 1.1529x over previous
#include <cuda_runtime.h>
#include <cuda_bf16.h>
#include <stdint.h>
#include <cstdint>
#include <math.h>

#define Bb 2
#define C 256
#define Nn 8192
#define G 32
#define CPG 8
#define TQ 128
#define TK 64
#define NT (Nn / TK)   // 128 key tiles

// Scratch (no allocations allowed)
__device__ __nv_bfloat16 d_q[(size_t)Bb * Nn * C];     // [b][n][c]
__device__ __nv_bfloat16 d_k[(size_t)Bb * Nn * C];     // [b][n][c]
__device__ __nv_bfloat16 d_v[(size_t)Bb * C * Nn];     // [b][c][n]
__device__ __nv_bfloat16 d_attno[(size_t)Bb * Nn * C]; // [b][n][c] bf16
__device__ float d_ga[Bb * C];
__device__ float d_gb[Bb * C];

// ---------------------------------------------------------------------------
__device__ __forceinline__ uint32_t smem_u32(const void* p) {
    uint32_t a;
    asm("{ .reg .u64 t; cvta.to.shared.u64 t, %1; cvt.u32.u64 %0, t; }" : "=r"(a) : "l"(p));
    return a;
}
__device__ __forceinline__ void ldsm4(uint32_t a, uint32_t& d0, uint32_t& d1,
                                      uint32_t& d2, uint32_t& d3) {
    asm volatile("ldmatrix.sync.aligned.m8n8.x4.shared.b16 {%0,%1,%2,%3}, [%4];"
                 : "=r"(d0), "=r"(d1), "=r"(d2), "=r"(d3) : "r"(a));
}
__device__ __forceinline__ void mma_bf16(float& c0, float& c1, float& c2, float& c3,
                                         uint32_t a0, uint32_t a1, uint32_t a2, uint32_t a3,
                                         uint32_t b0, uint32_t b1) {
    asm volatile("mma.sync.aligned.m16n8k16.row.col.f32.bf16.bf16.f32 "
                 "{%0,%1,%2,%3}, {%4,%5,%6,%7}, {%8,%9}, {%0,%1,%2,%3};"
                 : "+f"(c0), "+f"(c1), "+f"(c2), "+f"(c3)
                 : "r"(a0), "r"(a1), "r"(a2), "r"(a3), "r"(b0), "r"(b1));
}
__device__ __forceinline__ void cpa16(uint32_t dst, const void* src) {
    asm volatile("cp.async.cg.shared.global [%0], [%1], 16;" :: "r"(dst), "l"(src) : "memory");
}
#define CP_COMMIT() asm volatile("cp.async.commit_group;" ::: "memory")
#define CP_WAIT(n)  asm volatile("cp.async.wait_group %0;" :: "n"(n) : "memory")

__device__ __forceinline__ uint32_t packbf2(float a, float b) {
    __nv_bfloat162 h = __float22bfloat162_rn(make_float2(a, b));
    return *(uint32_t*)&h;
}
__device__ __forceinline__ uint32_t packu16(uint32_t lo, uint32_t hi) {
    return (lo & 0xffffu) | (hi << 16);
}

// ---------------------------------------------------------------------------
// Kernel 1: GroupNorm statistics -> per-channel affine params
// ---------------------------------------------------------------------------
__global__ __launch_bounds__(256) void gn_stats(const float* __restrict__ x,
                                                const float* __restrict__ nw,
                                                const float* __restrict__ nb) {
    int b = blockIdx.x >> 5, g = blockIdx.x & 31;
    const float4* p = (const float4*)(x + ((size_t)b * C + (size_t)g * CPG) * Nn);
    float s = 0.f, ss = 0.f;
    const int total4 = CPG * Nn / 4;
    for (int i = threadIdx.x; i < total4; i += 256) {
        float4 v4 = p[i];
        s += v4.x + v4.y + v4.z + v4.w;
        ss += v4.x * v4.x + v4.y * v4.y + v4.z * v4.z + v4.w * v4.w;
    }
    for (int off = 16; off; off >>= 1) {
        s += __shfl_xor_sync(0xffffffffu, s, off);
        ss += __shfl_xor_sync(0xffffffffu, ss, off);
    }
    __shared__ float rsm[8], rssm[8];
    int w = threadIdx.x >> 5, ln = threadIdx.x & 31;
    if (ln == 0) { rsm[w] = s; rssm[w] = ss; }
    __syncthreads();
    if (threadIdx.x < 8) {
        s = rsm[threadIdx.x]; ss = rssm[threadIdx.x];
        for (int off = 4; off; off >>= 1) {
            s += __shfl_xor_sync(0xffu, s, off);
            ss += __shfl_xor_sync(0xffu, ss, off);
        }
        float mean = s * (1.f / 65536.f);
        float var = ss * (1.f / 65536.f) - mean * mean;
        float rstd = rsqrtf(var + 1e-5f);
        int c = g * CPG + threadIdx.x;
        float wv = nw[c];
        d_ga[b * C + c] = rstd * wv;
        d_gb[b * C + c] = nb[c] - mean * rstd * wv;
    }
}

// ---------------------------------------------------------------------------
// Kernel 2: QKV GEMM, single pass over x. Dynamic smem:
//   [0, 33792)        h bf16 [64n][256c] stride 528
//   [33792, 54272)    W chunk bf16 [256o][32k] stride 80
//   [54272, 72704)    fp32 x stage / epilogue scratch (18432)
// ---------------------------------------------------------------------------
#define QH_OFF 0u
#define QW_OFF 33792u
#define QC_OFF 54272u
#define SMEM_QKV 72704

__global__ __launch_bounds__(256) void qkv_mma(const float* __restrict__ x,
                                               const float* __restrict__ W,
                                               const float* __restrict__ bias) {
    extern __shared__ __align__(16) char qsm[];
    char* hs_ = qsm + QH_OFF;
    char* ws_ = qsm + QW_OFF;
    char* sc_ = qsm + QC_OFF;
    const uint32_t shs = smem_u32(hs_), sws = smem_u32(ws_);
    const int b = blockIdx.z, n0 = blockIdx.x * 64;
    const int t = threadIdx.x, w = t >> 5, lane = t & 31;
    const float* xb = x + (size_t)b * C * Nn;

    // ---- build h tile once: 8 chunks of 32 channels ----
    for (int k0 = 0; k0 < C; k0 += 32) {
#pragma unroll
        for (int i = 0; i < 2; i++) {
            int idx = t + i * 256, cc = idx >> 4, n4 = idx & 15;
            int c = k0 + cc;
            float av = d_ga[b * C + c], bv = d_gb[b * C + c];
            float4 v4 = *(const float4*)&xb[(size_t)c * Nn + n0 + n4 * 4];
            *(float4*)(sc_ + (cc * 68 + n4 * 4) * 4) =
                make_float4(v4.x * av + bv, v4.y * av + bv, v4.z * av + bv, v4.w * av + bv);
        }
        __syncthreads();
        {
            int n = t & 63, kg = t >> 6;
            float f[8];
#pragma unroll
            for (int j = 0; j < 8; j++)
                f[j] = *(float*)(sc_ + ((kg * 8 + j) * 68 + n) * 4);
            uint4 u;
            u.x = packbf2(f[0], f[1]); u.y = packbf2(f[2], f[3]);
            u.z = packbf2(f[4], f[5]); u.w = packbf2(f[6], f[7]);
            *(uint4*)(hs_ + n * 528 + k0 * 2 + kg * 16) = u;
        }
        __syncthreads();
    }

    const int qb = w * 16;
    const uint32_t aW0 = sws + (qb + (lane & 15)) * 80 + ((lane >> 4) << 4);
    const uint32_t aW1 = aW0 + 128 * 80;
    const uint32_t bHrow = (lane & 7) + ((lane >> 4) << 3);
    const uint32_t bHcol = (lane & 8) ? 16u : 0u;
    const int r = qb + (lane >> 2);

    for (int s = 0; s < 3; s++) {
        const float* Ws = W + (size_t)s * 256 * C;
        float acc[2][4][2][4] = {};

        for (int k0 = 0; k0 < C; k0 += 32) {
#pragma unroll
            for (int i = 0; i < 8; i++) {
                int idx = t + i * 256, oo = idx >> 3, kg = idx & 7;
                float4 v4 = *(const float4*)&Ws[(size_t)oo * C + k0 + kg * 4];
                uint32_t* dp = (uint32_t*)(ws_ + oo * 80 + kg * 8);
                dp[0] = packbf2(v4.x, v4.y);
                dp[1] = packbf2(v4.z, v4.w);
            }
            __syncthreads();
#pragma unroll
            for (int kt = 0; kt < 2; kt++) {
                uint32_t a0, a1, a2, a3, c0, c1, c2, c3;
                ldsm4(aW0 + kt * 32, a0, a1, a2, a3);
                ldsm4(aW1 + kt * 32, c0, c1, c2, c3);
#pragma unroll
                for (int nbk = 0; nbk < 4; nbk++) {
                    uint32_t b0, b1, b2, b3;
                    ldsm4(shs + (nbk * 16 + bHrow) * 528 + k0 * 2 + kt * 32 + bHcol,
                          b0, b1, b2, b3);
                    mma_bf16(acc[0][nbk][0][0], acc[0][nbk][0][1], acc[0][nbk][0][2], acc[0][nbk][0][3],
                             a0, a1, a2, a3, b0, b1);
                    mma_bf16(acc[0][nbk][1][0], acc[0][nbk][1][1], acc[0][nbk][1][2], acc[0][nbk][1][3],
                             a0, a1, a2, a3, b2, b3);
                    mma_bf16(acc[1][nbk][0][0], acc[1][nbk][0][1], acc[1][nbk][0][2], acc[1][nbk][0][3],
                             c0, c1, c2, c3, b0, b1);
                    mma_bf16(acc[1][nbk][1][0], acc[1][nbk][1][1], acc[1][nbk][1][2], acc[1][nbk][1][3],
                             c0, c1, c2, c3, b2, b3);
                }
            }
            __syncthreads();
        }

        if (s < 2) {
            // q/k: per-half smem transpose -> [n][C]
            __nv_bfloat16* dst = ((s == 0) ? d_q : d_k) + (size_t)b * Nn * C;
#pragma unroll
            for (int h = 0; h < 2; h++) {
                float bi0 = bias[s * 256 + h * 128 + r];
                float bi1 = bias[s * 256 + h * 128 + r + 8];
#pragma unroll
                for (int nbk = 0; nbk < 4; nbk++)
#pragma unroll
                    for (int nn = 0; nn < 2; nn++) {
                        int n = nbk * 16 + nn * 8 + 2 * (lane & 3);
                        *(uint32_t*)(sc_ + r * 144 + n * 2) =
                            packbf2(acc[h][nbk][nn][0] + bi0, acc[h][nbk][nn][1] + bi0);
                        *(uint32_t*)(sc_ + (r + 8) * 144 + n * 2) =
                            packbf2(acc[h][nbk][nn][2] + bi1, acc[h][nbk][nn][3] + bi1);
                    }
                __syncthreads();
#pragma unroll
                for (int i = 0; i < 4; i++) {
                    int idx = t + i * 256, n = idx & 63, og = idx >> 6;
                    uint32_t hh[8];
#pragma unroll
                    for (int j = 0; j < 8; j++)
                        hh[j] = *(uint16_t*)(sc_ + (og * 8 + j) * 144 + n * 2);
                    uint4 u;
                    u.x = packu16(hh[0], hh[1]); u.y = packu16(hh[2], hh[3]);
                    u.z = packu16(hh[4], hh[5]); u.w = packu16(hh[6], hh[7]);
                    *(uint4*)&dst[(size_t)(n0 + n) * C + h * 128 + og * 8] = u;
                }
                __syncthreads();
            }
        } else {
            // v: direct [c][n]
            __nv_bfloat16* dst = d_v + (size_t)b * C * Nn;
#pragma unroll
            for (int h = 0; h < 2; h++) {
                int ch = h * 128 + r;
                float bi0 = bias[512 + ch], bi1 = bias[512 + ch + 8];
#pragma unroll
                for (int nbk = 0; nbk < 4; nbk++)
#pragma unroll
                    for (int nn = 0; nn < 2; nn++) {
                        int n = n0 + nbk * 16 + nn * 8 + 2 * (lane & 3);
                        *(uint32_t*)&dst[(size_t)ch * Nn + n] =
                            packbf2(acc[h][nbk][nn][0] + bi0, acc[h][nbk][nn][1] + bi0);
                        *(uint32_t*)&dst[(size_t)(ch + 8) * Nn + n] =
                            packbf2(acc[h][nbk][nn][2] + bi1, acc[h][nbk][nn][3] + bi1);
                    }
            }
        }
    }
}

// ---------------------------------------------------------------------------
// Kernel 3: bf16 flash attention, FA2 register-P. TQ=128, TK=64 (round-11).
// ---------------------------------------------------------------------------
#define QS_OFF  0u
#define KS0_OFF 67584u
#define KS1_OFF 101376u
#define VS0_OFF 135168u
#define VS1_OFF 172032u
#define SMEM_FLASH 208896

__global__ __launch_bounds__(256, 1) void flash_mma() {
    extern __shared__ __align__(16) char sm[];
    const uint32_t sb = smem_u32(sm);
    const int t = threadIdx.x, w = t >> 5, lane = t & 31;
    const int b = blockIdx.y, q0 = blockIdx.x * TQ;
    const __nv_bfloat16* qg = d_q + (size_t)b * Nn * C;
    const __nv_bfloat16* kg = d_k + (size_t)b * Nn * C;
    const __nv_bfloat16* vg = d_v + (size_t)b * C * Nn;

#pragma unroll
    for (int i = 0; i < 16; i++) {
        int g = t + i * 256, row = g >> 5, ck = g & 31;
        cpa16(sb + QS_OFF + row * 528 + ck * 16, qg + (size_t)(q0 + row) * C + ck * 8);
    }
    CP_COMMIT();
#pragma unroll
    for (int i = 0; i < 8; i++) {
        int g = t + i * 256, row = g >> 5, ck = g & 31;
        cpa16(sb + KS0_OFF + row * 528 + ck * 16, kg + (size_t)row * C + ck * 8);
    }
#pragma unroll
    for (int i = 0; i < 8; i++) {
        int g = t + i * 256, ch = g >> 3, ck = g & 7;
        cpa16(sb + VS0_OFF + ch * 144 + ck * 16, vg + (size_t)ch * Nn + ck * 8);
    }
    CP_COMMIT();

    float O[32][4];
#pragma unroll
    for (int m = 0; m < 32; m++)
#pragma unroll
        for (int c = 0; c < 4; c++) O[m][c] = 0.f;
    float l0 = 0.f, l1 = 0.f;

    const int qb = w * 16;
    const uint32_t aQ = sb + QS_OFF + (qb + (lane & 15)) * 528 + ((lane >> 4) * 8) * 2;
    const uint32_t bKrow = (lane & 7) + ((lane >> 4) << 3);
    const uint32_t bKcol = (lane & 8) ? 16u : 0u;

    for (int tile = 0; tile < NT; tile++) {
        const uint32_t kcur = sb + ((tile & 1) ? KS1_OFF : KS0_OFF);
        const uint32_t vcur = sb + ((tile & 1) ? VS1_OFF : VS0_OFF);
        if (tile + 1 < NT) {
            const uint32_t kn = sb + (((tile + 1) & 1) ? KS1_OFF : KS0_OFF);
            const uint32_t vn = sb + (((tile + 1) & 1) ? VS1_OFF : VS0_OFF);
            const int kk1 = (tile + 1) * TK;
#pragma unroll
            for (int i = 0; i < 8; i++) {
                int g = t + i * 256, row = g >> 5, ck = g & 31;
                cpa16(kn + row * 528 + ck * 16, kg + (size_t)(kk1 + row) * C + ck * 8);
            }
#pragma unroll
            for (int i = 0; i < 8; i++) {
                int g = t + i * 256, ch = g >> 3, ck = g & 7;
                cpa16(vn + ch * 144 + ck * 16, vg + (size_t)ch * Nn + kk1 + ck * 8);
            }
            CP_COMMIT();
            CP_WAIT(1);
        } else {
            CP_WAIT(0);
        }
        __syncthreads();

        // ---- S = Q K^T ----
        float S[8][4];
#pragma unroll
        for (int nt = 0; nt < 8; nt++)
#pragma unroll
            for (int c = 0; c < 4; c++) S[nt][c] = 0.f;
#pragma unroll
        for (int kt = 0; kt < 16; kt++) {
            uint32_t a0, a1, a2, a3;
            ldsm4(aQ + kt * 32, a0, a1, a2, a3);
#pragma unroll
            for (int kb = 0; kb < 4; kb++) {
                uint32_t b0, b1, b2, b3;
                ldsm4(kcur + (kb * 16 + bKrow) * 528 + kt * 32 + bKcol, b0, b1, b2, b3);
                mma_bf16(S[2 * kb][0], S[2 * kb][1], S[2 * kb][2], S[2 * kb][3],
                         a0, a1, a2, a3, b0, b1);
                mma_bf16(S[2 * kb + 1][0], S[2 * kb + 1][1], S[2 * kb + 1][2], S[2 * kb + 1][3],
                         a0, a1, a2, a3, b2, b3);
            }
        }

        // ---- softmax (no max) -> A-fragments in registers ----
        uint32_t aP[4][4];
#pragma unroll
        for (int ka = 0; ka < 4; ka++) {
            float p00 = __expf(S[2 * ka][0] * 0.0625f);
            float p01 = __expf(S[2 * ka][1] * 0.0625f);
            float p02 = __expf(S[2 * ka][2] * 0.0625f);
            float p03 = __expf(S[2 * ka][3] * 0.0625f);
            float p10 = __expf(S[2 * ka + 1][0] * 0.0625f);
            float p11 = __expf(S[2 * ka + 1][1] * 0.0625f);
            float p12 = __expf(S[2 * ka + 1][2] * 0.0625f);
            float p13 = __expf(S[2 * ka + 1][3] * 0.0625f);
            l0 += (p00 + p01) + (p10 + p11);
            l1 += (p02 + p03) + (p12 + p13);
            aP[ka][0] = packbf2(p00, p01);
            aP[ka][1] = packbf2(p02, p03);
            aP[ka][2] = packbf2(p10, p11);
            aP[ka][3] = packbf2(p12, p13);
        }

        // ---- O += P V^T ----
#pragma unroll
        for (int cb = 0; cb < 16; cb++) {
            uint32_t vbase = vcur + (cb * 16 + bKrow) * 144 + bKcol;
#pragma unroll
            for (int ka = 0; ka < 4; ka++) {
                uint32_t b0, b1, b2, b3;
                ldsm4(vbase + ka * 32, b0, b1, b2, b3);
                mma_bf16(O[2 * cb][0], O[2 * cb][1], O[2 * cb][2], O[2 * cb][3],
                         aP[ka][0], aP[ka][1], aP[ka][2], aP[ka][3], b0, b1);
                mma_bf16(O[2 * cb + 1][0], O[2 * cb + 1][1], O[2 * cb + 1][2], O[2 * cb + 1][3],
                         aP[ka][0], aP[ka][1], aP[ka][2], aP[ka][3], b2, b3);
            }
        }
        __syncthreads();
    }

    // ---- reduce l across quad, normalize, store [n][c] ----
    l0 += __shfl_xor_sync(0xffffffffu, l0, 1);
    l0 += __shfl_xor_sync(0xffffffffu, l0, 2);
    l1 += __shfl_xor_sync(0xffffffffu, l1, 1);
    l1 += __shfl_xor_sync(0xffffffffu, l1, 2);
    float inv0 = 1.f / l0, inv1 = 1.f / l1;
    __nv_bfloat16* ao = d_attno + (size_t)b * Nn * C;
    int nr = q0 + qb + (lane >> 2);
#pragma unroll
    for (int ob = 0; ob < 32; ob++) {
        int cc = (ob >> 1) * 16 + (ob & 1) * 8 + 2 * (lane & 3);
        *(uint32_t*)&ao[(size_t)nr * C + cc] = packbf2(O[ob][0] * inv0, O[ob][1] * inv0);
        *(uint32_t*)&ao[(size_t)(nr + 8) * C + cc] = packbf2(O[ob][2] * inv1, O[ob][3] * inv1);
    }
}

// ---------------------------------------------------------------------------
// Kernel 4: projection GEMM + bias + residual (attno [n][c] native B layout)
// ---------------------------------------------------------------------------
__global__ __launch_bounds__(256) void proj_mma(const float* __restrict__ x,
                                                const float* __restrict__ W,
                                                const float* __restrict__ bias,
                                                float* __restrict__ out) {
    __shared__ __align__(16) char ws_[128 * 80];
    __shared__ __align__(16) char hs_[64 * 80];
    const uint32_t sws = smem_u32(ws_), shs = smem_u32(hs_);
    const int b = blockIdx.z, o0 = blockIdx.y * 128, n0 = blockIdx.x * 64;
    const int t = threadIdx.x, w = t >> 5, lane = t & 31;
    const __nv_bfloat16* ab = d_attno + (size_t)b * Nn * C;

    const int qb = w * 16;
    const uint32_t aW = sws + (qb + (lane & 15)) * 80 + ((lane >> 4) << 4);
    const uint32_t bHrow = (lane & 7) + ((lane >> 4) << 3);
    const uint32_t bHcol = (lane & 8) ? 16u : 0u;

    float acc[4][2][4] = {};

    for (int k0 = 0; k0 < C; k0 += 32) {
        {
            int nn = t >> 2, ck = t & 3;
            cpa16(shs + nn * 80 + ck * 16, ab + (size_t)(n0 + nn) * C + k0 + ck * 8);
        }
        CP_COMMIT();
#pragma unroll
        for (int i = 0; i < 4; i++) {
            int idx = t + i * 256, oo = idx >> 3, kg = idx & 7;
            float4 v4 = *(const float4*)&W[(size_t)(o0 + oo) * C + k0 + kg * 4];
            uint32_t* dp = (uint32_t*)(ws_ + oo * 80 + kg * 8);
            dp[0] = packbf2(v4.x, v4.y);
            dp[1] = packbf2(v4.z, v4.w);
        }
        CP_WAIT(0);
        __syncthreads();
#pragma unroll
        for (int kt = 0; kt < 2; kt++) {
            uint32_t a0, a1, a2, a3;
            ldsm4(aW + kt * 32, a0, a1, a2, a3);
#pragma unroll
            for (int nbk = 0; nbk < 4; nbk++) {
                uint32_t b0, b1, b2, b3;
                ldsm4(shs + (nbk * 16 + bHrow) * 80 + kt * 32 + bHcol, b0, b1, b2, b3);
                mma_bf16(acc[nbk][0][0], acc[nbk][0][1], acc[nbk][0][2], acc[nbk][0][3],
                         a0, a1, a2, a3, b0, b1);
                mma_bf16(acc[nbk][1][0], acc[nbk][1][1], acc[nbk][1][2], acc[nbk][1][3],
                         a0, a1, a2, a3, b2, b3);
            }
        }
        __syncthreads();
    }

    const int r = qb + (lane >> 2);
    const float bi0 = bias[o0 + r], bi1 = bias[o0 + r + 8];
    size_t row0 = ((size_t)b * C + o0 + r) * Nn + n0;
    size_t row1 = ((size_t)b * C + o0 + r + 8) * Nn + n0;
#pragma unroll
    for (int nbk = 0; nbk < 4; nbk++)
#pragma unroll
        for (int nn = 0; nn < 2; nn++) {
            int n = nbk * 16 + nn * 8 + 2 * (lane & 3);
            float2 x0 = *(const float2*)&x[row0 + n];
            float2 x1 = *(const float2*)&x[row1 + n];
            *(float2*)&out[row0 + n] = make_float2(x0.x + acc[nbk][nn][0] + bi0,
                                                   x0.y + acc[nbk][nn][1] + bi0);
            *(float2*)&out[row1 + n] = make_float2(x1.x + acc[nbk][nn][2] + bi1,
                                                   x1.y + acc[nbk][nn][3] + bi1);
        }
}

// ---------------------------------------------------------------------------
extern "C" void kernel_launch(void* const* d_in, const int* in_sizes, int n_in,
                              void* d_out, int out_size) {
    const float* x  = (const float*)d_in[0];
    const float* nw = (const float*)d_in[1];
    const float* nb = (const float*)d_in[2];
    const float* qw = (const float*)d_in[3];
    const float* qb = (const float*)d_in[4];
    const float* pw = (const float*)d_in[5];
    const float* pb = (const float*)d_in[6];
    float* out = (float*)d_out;

    cudaFuncSetAttribute(flash_mma, cudaFuncAttributeMaxDynamicSharedMemorySize,
                         SMEM_FLASH);
    cudaFuncSetAttribute(qkv_mma, cudaFuncAttributeMaxDynamicSharedMemorySize,
                         SMEM_QKV);

    gn_stats<<<Bb * G, 256>>>(x, nw, nb);
    qkv_mma<<<dim3(Nn / 64, 1, Bb), 256, SMEM_QKV>>>(x, qw, qb);
    flash_mma<<<dim3(Nn / TQ, Bb), 256, SMEM_FLASH>>>();
    proj_mma<<<dim3(Nn / 64, C / 128, Bb), 256>>>(x, pw, pb, out);
}

// round 16
// speedup vs baseline: 1.1560x; 1.0027x over previous
#include <cuda_runtime.h>
#include <cuda_bf16.h>
#include <stdint.h>
#include <cstdint>
#include <math.h>

#define Bb 2
#define C 256
#define Nn 8192
#define G 32
#define CPG 8
#define TQ 128
#define TK 64
#define NT (Nn / TK)   // 128 key tiles

// Scratch (no allocations allowed)
__device__ __nv_bfloat16 d_q[(size_t)Bb * Nn * C];     // [b][n][c]
__device__ __nv_bfloat16 d_k[(size_t)Bb * Nn * C];     // [b][n][c]
__device__ __nv_bfloat16 d_v[(size_t)Bb * C * Nn];     // [b][c][n]
__device__ __nv_bfloat16 d_attno[(size_t)Bb * Nn * C]; // [b][n][c] bf16
__device__ __nv_bfloat16 d_wqkv[768 * C];              // bf16 qkv weights
__device__ __nv_bfloat16 d_wproj[C * C];               // bf16 proj weights
__device__ float d_ga[Bb * C];
__device__ float d_gb[Bb * C];

// ---------------------------------------------------------------------------
__device__ __forceinline__ uint32_t smem_u32(const void* p) {
    uint32_t a;
    asm("{ .reg .u64 t; cvta.to.shared.u64 t, %1; cvt.u32.u64 %0, t; }" : "=r"(a) : "l"(p));
    return a;
}
__device__ __forceinline__ void ldsm4(uint32_t a, uint32_t& d0, uint32_t& d1,
                                      uint32_t& d2, uint32_t& d3) {
    asm volatile("ldmatrix.sync.aligned.m8n8.x4.shared.b16 {%0,%1,%2,%3}, [%4];"
                 : "=r"(d0), "=r"(d1), "=r"(d2), "=r"(d3) : "r"(a));
}
__device__ __forceinline__ void mma_bf16(float& c0, float& c1, float& c2, float& c3,
                                         uint32_t a0, uint32_t a1, uint32_t a2, uint32_t a3,
                                         uint32_t b0, uint32_t b1) {
    asm volatile("mma.sync.aligned.m16n8k16.row.col.f32.bf16.bf16.f32 "
                 "{%0,%1,%2,%3}, {%4,%5,%6,%7}, {%8,%9}, {%0,%1,%2,%3};"
                 : "+f"(c0), "+f"(c1), "+f"(c2), "+f"(c3)
                 : "r"(a0), "r"(a1), "r"(a2), "r"(a3), "r"(b0), "r"(b1));
}
__device__ __forceinline__ void cpa16(uint32_t dst, const void* src) {
    asm volatile("cp.async.cg.shared.global [%0], [%1], 16;" :: "r"(dst), "l"(src) : "memory");
}
#define CP_COMMIT() asm volatile("cp.async.commit_group;" ::: "memory")
#define CP_WAIT(n)  asm volatile("cp.async.wait_group %0;" :: "n"(n) : "memory")

__device__ __forceinline__ uint32_t packbf2(float a, float b) {
    __nv_bfloat162 h = __float22bfloat162_rn(make_float2(a, b));
    return *(uint32_t*)&h;
}
__device__ __forceinline__ uint32_t packu16(uint32_t lo, uint32_t hi) {
    return (lo & 0xffffu) | (hi << 16);
}

// ---------------------------------------------------------------------------
// Kernel 0: W fp32 -> bf16 pre-convert (qkv 768x256 then proj 256x256)
// ---------------------------------------------------------------------------
__global__ __launch_bounds__(256) void wconv(const float* __restrict__ qw,
                                             const float* __restrict__ pw) {
    int idx = blockIdx.x * 256 + threadIdx.x;   // group of 4 elems
    if (idx < 49152) {
        float4 v4 = *(const float4*)&qw[(size_t)idx * 4];
        uint32_t* dp = (uint32_t*)&d_wqkv[(size_t)idx * 4];
        dp[0] = packbf2(v4.x, v4.y);
        dp[1] = packbf2(v4.z, v4.w);
    } else {
        int j = idx - 49152;
        float4 v4 = *(const float4*)&pw[(size_t)j * 4];
        uint32_t* dp = (uint32_t*)&d_wproj[(size_t)j * 4];
        dp[0] = packbf2(v4.x, v4.y);
        dp[1] = packbf2(v4.z, v4.w);
    }
}

// ---------------------------------------------------------------------------
// Kernel 1: GroupNorm statistics -> per-channel affine params
// ---------------------------------------------------------------------------
__global__ __launch_bounds__(256) void gn_stats(const float* __restrict__ x,
                                                const float* __restrict__ nw,
                                                const float* __restrict__ nb) {
    int b = blockIdx.x >> 5, g = blockIdx.x & 31;
    const float4* p = (const float4*)(x + ((size_t)b * C + (size_t)g * CPG) * Nn);
    float s = 0.f, ss = 0.f;
    const int total4 = CPG * Nn / 4;
    for (int i = threadIdx.x; i < total4; i += 256) {
        float4 v4 = p[i];
        s += v4.x + v4.y + v4.z + v4.w;
        ss += v4.x * v4.x + v4.y * v4.y + v4.z * v4.z + v4.w * v4.w;
    }
    for (int off = 16; off; off >>= 1) {
        s += __shfl_xor_sync(0xffffffffu, s, off);
        ss += __shfl_xor_sync(0xffffffffu, ss, off);
    }
    __shared__ float rsm[8], rssm[8];
    int w = threadIdx.x >> 5, ln = threadIdx.x & 31;
    if (ln == 0) { rsm[w] = s; rssm[w] = ss; }
    __syncthreads();
    if (threadIdx.x < 8) {
        s = rsm[threadIdx.x]; ss = rssm[threadIdx.x];
        for (int off = 4; off; off >>= 1) {
            s += __shfl_xor_sync(0xffu, s, off);
            ss += __shfl_xor_sync(0xffu, ss, off);
        }
        float mean = s * (1.f / 65536.f);
        float var = ss * (1.f / 65536.f) - mean * mean;
        float rstd = rsqrtf(var + 1e-5f);
        int c = g * CPG + threadIdx.x;
        float wv = nw[c];
        d_ga[b * C + c] = rstd * wv;
        d_gb[b * C + c] = nb[c] - mean * rstd * wv;
    }
}

// ---------------------------------------------------------------------------
// Kernel 2: QKV GEMM, single pass over x, cp.async double-buffered W (bf16).
// Dynamic smem: h [0,33792) | W 2x20480 [33792,74752) | scratch [74752,93184)
// ---------------------------------------------------------------------------
#define QH_OFF 0u
#define QW_OFF 33792u
#define QC_OFF 74752u
#define SMEM_QKV 93184

__global__ __launch_bounds__(256) void qkv_mma(const float* __restrict__ x,
                                               const float* __restrict__ bias) {
    extern __shared__ __align__(16) char qsm[];
    char* hs_ = qsm + QH_OFF;
    char* sc_ = qsm + QC_OFF;
    const uint32_t shs = smem_u32(hs_);
    const uint32_t sw0 = shs + QW_OFF;        // W buf0 (hs_ is at offset 0)
    const int b = blockIdx.z, n0 = blockIdx.x * 64;
    const int t = threadIdx.x, w = t >> 5, lane = t & 31;
    const float* xb = x + (size_t)b * C * Nn;

    // ---- build h tile once: 8 chunks of 32 channels ----
    for (int k0 = 0; k0 < C; k0 += 32) {
#pragma unroll
        for (int i = 0; i < 2; i++) {
            int idx = t + i * 256, cc = idx >> 4, n4 = idx & 15;
            int c = k0 + cc;
            float av = d_ga[b * C + c], bv = d_gb[b * C + c];
            float4 v4 = *(const float4*)&xb[(size_t)c * Nn + n0 + n4 * 4];
            *(float4*)(sc_ + (cc * 68 + n4 * 4) * 4) =
                make_float4(v4.x * av + bv, v4.y * av + bv, v4.z * av + bv, v4.w * av + bv);
        }
        __syncthreads();
        {
            int n = t & 63, kg = t >> 6;
            float f[8];
#pragma unroll
            for (int j = 0; j < 8; j++)
                f[j] = *(float*)(sc_ + ((kg * 8 + j) * 68 + n) * 4);
            uint4 u;
            u.x = packbf2(f[0], f[1]); u.y = packbf2(f[2], f[3]);
            u.z = packbf2(f[4], f[5]); u.w = packbf2(f[6], f[7]);
            *(uint4*)(hs_ + n * 528 + k0 * 2 + kg * 16) = u;
        }
        __syncthreads();
    }

    const int qb = w * 16;
    const uint32_t bHrow = (lane & 7) + ((lane >> 4) << 3);
    const uint32_t bHcol = (lane & 8) ? 16u : 0u;
    const int r = qb + (lane >> 2);
    const uint32_t aWl = (qb + (lane & 15)) * 80 + ((lane >> 4) << 4);

    for (int s = 0; s < 3; s++) {
        const __nv_bfloat16* Wb = d_wqkv + (size_t)s * 256 * C;
        float acc[2][4][2][4] = {};

        // stage chunk 0 -> buf0
#pragma unroll
        for (int i = 0; i < 4; i++) {
            int idx = t + i * 256, row = idx >> 2, seg = idx & 3;
            cpa16(sw0 + row * 80 + seg * 16, Wb + (size_t)row * C + seg * 8);
        }
        CP_COMMIT();

        for (int kc = 0; kc < 8; kc++) {
            const uint32_t wcur = sw0 + (kc & 1) * 20480;
            if (kc < 7) {
                const uint32_t wn = sw0 + ((kc + 1) & 1) * 20480;
                const int k1 = (kc + 1) * 32;
#pragma unroll
                for (int i = 0; i < 4; i++) {
                    int idx = t + i * 256, row = idx >> 2, seg = idx & 3;
                    cpa16(wn + row * 80 + seg * 16, Wb + (size_t)row * C + k1 + seg * 8);
                }
                CP_COMMIT();
                CP_WAIT(1);
            } else {
                CP_WAIT(0);
            }
            __syncthreads();
#pragma unroll
            for (int kt = 0; kt < 2; kt++) {
                uint32_t a0, a1, a2, a3, c0, c1, c2, c3;
                ldsm4(wcur + aWl + kt * 32, a0, a1, a2, a3);
                ldsm4(wcur + aWl + 128 * 80 + kt * 32, c0, c1, c2, c3);
#pragma unroll
                for (int nbk = 0; nbk < 4; nbk++) {
                    uint32_t b0, b1, b2, b3;
                    ldsm4(shs + (nbk * 16 + bHrow) * 528 + kc * 64 + kt * 32 + bHcol,
                          b0, b1, b2, b3);
                    mma_bf16(acc[0][nbk][0][0], acc[0][nbk][0][1], acc[0][nbk][0][2], acc[0][nbk][0][3],
                             a0, a1, a2, a3, b0, b1);
                    mma_bf16(acc[0][nbk][1][0], acc[0][nbk][1][1], acc[0][nbk][1][2], acc[0][nbk][1][3],
                             a0, a1, a2, a3, b2, b3);
                    mma_bf16(acc[1][nbk][0][0], acc[1][nbk][0][1], acc[1][nbk][0][2], acc[1][nbk][0][3],
                             c0, c1, c2, c3, b0, b1);
                    mma_bf16(acc[1][nbk][1][0], acc[1][nbk][1][1], acc[1][nbk][1][2], acc[1][nbk][1][3],
                             c0, c1, c2, c3, b2, b3);
                }
            }
            __syncthreads();
        }

        if (s < 2) {
            // q/k: per-half smem transpose -> [n][C]
            __nv_bfloat16* dst = ((s == 0) ? d_q : d_k) + (size_t)b * Nn * C;
#pragma unroll
            for (int h = 0; h < 2; h++) {
                float bi0 = bias[s * 256 + h * 128 + r];
                float bi1 = bias[s * 256 + h * 128 + r + 8];
#pragma unroll
                for (int nbk = 0; nbk < 4; nbk++)
#pragma unroll
                    for (int nn = 0; nn < 2; nn++) {
                        int n = nbk * 16 + nn * 8 + 2 * (lane & 3);
                        *(uint32_t*)(sc_ + r * 144 + n * 2) =
                            packbf2(acc[h][nbk][nn][0] + bi0, acc[h][nbk][nn][1] + bi0);
                        *(uint32_t*)(sc_ + (r + 8) * 144 + n * 2) =
                            packbf2(acc[h][nbk][nn][2] + bi1, acc[h][nbk][nn][3] + bi1);
                    }
                __syncthreads();
#pragma unroll
                for (int i = 0; i < 4; i++) {
                    int idx = t + i * 256, n = idx & 63, og = idx >> 6;
                    uint32_t hh[8];
#pragma unroll
                    for (int j = 0; j < 8; j++)
                        hh[j] = *(uint16_t*)(sc_ + (og * 8 + j) * 144 + n * 2);
                    uint4 u;
                    u.x = packu16(hh[0], hh[1]); u.y = packu16(hh[2], hh[3]);
                    u.z = packu16(hh[4], hh[5]); u.w = packu16(hh[6], hh[7]);
                    *(uint4*)&dst[(size_t)(n0 + n) * C + h * 128 + og * 8] = u;
                }
                __syncthreads();
            }
        } else {
            // v: direct [c][n]
            __nv_bfloat16* dst = d_v + (size_t)b * C * Nn;
#pragma unroll
            for (int h = 0; h < 2; h++) {
                int ch = h * 128 + r;
                float bi0 = bias[512 + ch], bi1 = bias[512 + ch + 8];
#pragma unroll
                for (int nbk = 0; nbk < 4; nbk++)
#pragma unroll
                    for (int nn = 0; nn < 2; nn++) {
                        int n = n0 + nbk * 16 + nn * 8 + 2 * (lane & 3);
                        *(uint32_t*)&dst[(size_t)ch * Nn + n] =
                            packbf2(acc[h][nbk][nn][0] + bi0, acc[h][nbk][nn][1] + bi0);
                        *(uint32_t*)&dst[(size_t)(ch + 8) * Nn + n] =
                            packbf2(acc[h][nbk][nn][2] + bi1, acc[h][nbk][nn][3] + bi1);
                    }
            }
        }
    }
}

// ---------------------------------------------------------------------------
// Kernel 3: bf16 flash attention, FA2 register-P. TQ=128, TK=64 (round-11).
// ---------------------------------------------------------------------------
#define QS_OFF  0u
#define KS0_OFF 67584u
#define KS1_OFF 101376u
#define VS0_OFF 135168u
#define VS1_OFF 172032u
#define SMEM_FLASH 208896

__global__ __launch_bounds__(256, 1) void flash_mma() {
    extern __shared__ __align__(16) char sm[];
    const uint32_t sb = smem_u32(sm);
    const int t = threadIdx.x, w = t >> 5, lane = t & 31;
    const int b = blockIdx.y, q0 = blockIdx.x * TQ;
    const __nv_bfloat16* qg = d_q + (size_t)b * Nn * C;
    const __nv_bfloat16* kg = d_k + (size_t)b * Nn * C;
    const __nv_bfloat16* vg = d_v + (size_t)b * C * Nn;

#pragma unroll
    for (int i = 0; i < 16; i++) {
        int g = t + i * 256, row = g >> 5, ck = g & 31;
        cpa16(sb + QS_OFF + row * 528 + ck * 16, qg + (size_t)(q0 + row) * C + ck * 8);
    }
    CP_COMMIT();
#pragma unroll
    for (int i = 0; i < 8; i++) {
        int g = t + i * 256, row = g >> 5, ck = g & 31;
        cpa16(sb + KS0_OFF + row * 528 + ck * 16, kg + (size_t)row * C + ck * 8);
    }
#pragma unroll
    for (int i = 0; i < 8; i++) {
        int g = t + i * 256, ch = g >> 3, ck = g & 7;
        cpa16(sb + VS0_OFF + ch * 144 + ck * 16, vg + (size_t)ch * Nn + ck * 8);
    }
    CP_COMMIT();

    float O[32][4];
#pragma unroll
    for (int m = 0; m < 32; m++)
#pragma unroll
        for (int c = 0; c < 4; c++) O[m][c] = 0.f;
    float l0 = 0.f, l1 = 0.f;

    const int qb = w * 16;
    const uint32_t aQ = sb + QS_OFF + (qb + (lane & 15)) * 528 + ((lane >> 4) * 8) * 2;
    const uint32_t bKrow = (lane & 7) + ((lane >> 4) << 3);
    const uint32_t bKcol = (lane & 8) ? 16u : 0u;

    for (int tile = 0; tile < NT; tile++) {
        const uint32_t kcur = sb + ((tile & 1) ? KS1_OFF : KS0_OFF);
        const uint32_t vcur = sb + ((tile & 1) ? VS1_OFF : VS0_OFF);
        if (tile + 1 < NT) {
            const uint32_t kn = sb + (((tile + 1) & 1) ? KS1_OFF : KS0_OFF);
            const uint32_t vn = sb + (((tile + 1) & 1) ? VS1_OFF : VS0_OFF);
            const int kk1 = (tile + 1) * TK;
#pragma unroll
            for (int i = 0; i < 8; i++) {
                int g = t + i * 256, row = g >> 5, ck = g & 31;
                cpa16(kn + row * 528 + ck * 16, kg + (size_t)(kk1 + row) * C + ck * 8);
            }
#pragma unroll
            for (int i = 0; i < 8; i++) {
                int g = t + i * 256, ch = g >> 3, ck = g & 7;
                cpa16(vn + ch * 144 + ck * 16, vg + (size_t)ch * Nn + kk1 + ck * 8);
            }
            CP_COMMIT();
            CP_WAIT(1);
        } else {
            CP_WAIT(0);
        }
        __syncthreads();

        // ---- S = Q K^T ----
        float S[8][4];
#pragma unroll
        for (int nt = 0; nt < 8; nt++)
#pragma unroll
            for (int c = 0; c < 4; c++) S[nt][c] = 0.f;
#pragma unroll
        for (int kt = 0; kt < 16; kt++) {
            uint32_t a0, a1, a2, a3;
            ldsm4(aQ + kt * 32, a0, a1, a2, a3);
#pragma unroll
            for (int kb = 0; kb < 4; kb++) {
                uint32_t b0, b1, b2, b3;
                ldsm4(kcur + (kb * 16 + bKrow) * 528 + kt * 32 + bKcol, b0, b1, b2, b3);
                mma_bf16(S[2 * kb][0], S[2 * kb][1], S[2 * kb][2], S[2 * kb][3],
                         a0, a1, a2, a3, b0, b1);
                mma_bf16(S[2 * kb + 1][0], S[2 * kb + 1][1], S[2 * kb + 1][2], S[2 * kb + 1][3],
                         a0, a1, a2, a3, b2, b3);
            }
        }

        // ---- softmax (no max) -> A-fragments in registers ----
        uint32_t aP[4][4];
#pragma unroll
        for (int ka = 0; ka < 4; ka++) {
            float p00 = __expf(S[2 * ka][0] * 0.0625f);
            float p01 = __expf(S[2 * ka][1] * 0.0625f);
            float p02 = __expf(S[2 * ka][2] * 0.0625f);
            float p03 = __expf(S[2 * ka][3] * 0.0625f);
            float p10 = __expf(S[2 * ka + 1][0] * 0.0625f);
            float p11 = __expf(S[2 * ka + 1][1] * 0.0625f);
            float p12 = __expf(S[2 * ka + 1][2] * 0.0625f);
            float p13 = __expf(S[2 * ka + 1][3] * 0.0625f);
            l0 += (p00 + p01) + (p10 + p11);
            l1 += (p02 + p03) + (p12 + p13);
            aP[ka][0] = packbf2(p00, p01);
            aP[ka][1] = packbf2(p02, p03);
            aP[ka][2] = packbf2(p10, p11);
            aP[ka][3] = packbf2(p12, p13);
        }

        // ---- O += P V^T ----
#pragma unroll
        for (int cb = 0; cb < 16; cb++) {
            uint32_t vbase = vcur + (cb * 16 + bKrow) * 144 + bKcol;
#pragma unroll
            for (int ka = 0; ka < 4; ka++) {
                uint32_t b0, b1, b2, b3;
                ldsm4(vbase + ka * 32, b0, b1, b2, b3);
                mma_bf16(O[2 * cb][0], O[2 * cb][1], O[2 * cb][2], O[2 * cb][3],
                         aP[ka][0], aP[ka][1], aP[ka][2], aP[ka][3], b0, b1);
                mma_bf16(O[2 * cb + 1][0], O[2 * cb + 1][1], O[2 * cb + 1][2], O[2 * cb + 1][3],
                         aP[ka][0], aP[ka][1], aP[ka][2], aP[ka][3], b2, b3);
            }
        }
        __syncthreads();
    }

    // ---- reduce l across quad, normalize, store [n][c] ----
    l0 += __shfl_xor_sync(0xffffffffu, l0, 1);
    l0 += __shfl_xor_sync(0xffffffffu, l0, 2);
    l1 += __shfl_xor_sync(0xffffffffu, l1, 1);
    l1 += __shfl_xor_sync(0xffffffffu, l1, 2);
    float inv0 = 1.f / l0, inv1 = 1.f / l1;
    __nv_bfloat16* ao = d_attno + (size_t)b * Nn * C;
    int nr = q0 + qb + (lane >> 2);
#pragma unroll
    for (int ob = 0; ob < 32; ob++) {
        int cc = (ob >> 1) * 16 + (ob & 1) * 8 + 2 * (lane & 3);
        *(uint32_t*)&ao[(size_t)nr * C + cc] = packbf2(O[ob][0] * inv0, O[ob][1] * inv0);
        *(uint32_t*)&ao[(size_t)(nr + 8) * C + cc] = packbf2(O[ob][2] * inv1, O[ob][3] * inv1);
    }
}

// ---------------------------------------------------------------------------
// Kernel 4: projection GEMM + bias + residual; W from pre-converted bf16.
// ---------------------------------------------------------------------------
__global__ __launch_bounds__(256) void proj_mma(const float* __restrict__ x,
                                                const float* __restrict__ bias,
                                                float* __restrict__ out) {
    __shared__ __align__(16) char ws_[128 * 80];
    __shared__ __align__(16) char hs_[64 * 80];
    const uint32_t sws = smem_u32(ws_), shs = smem_u32(hs_);
    const int b = blockIdx.z, o0 = blockIdx.y * 128, n0 = blockIdx.x * 64;
    const int t = threadIdx.x, w = t >> 5, lane = t & 31;
    const __nv_bfloat16* ab = d_attno + (size_t)b * Nn * C;

    const int qb = w * 16;
    const uint32_t aW = sws + (qb + (lane & 15)) * 80 + ((lane >> 4) << 4);
    const uint32_t bHrow = (lane & 7) + ((lane >> 4) << 3);
    const uint32_t bHcol = (lane & 8) ? 16u : 0u;

    float acc[4][2][4] = {};

    for (int k0 = 0; k0 < C; k0 += 32) {
        {
            int nn = t >> 2, ck = t & 3;
            cpa16(shs + nn * 80 + ck * 16, ab + (size_t)(n0 + nn) * C + k0 + ck * 8);
        }
#pragma unroll
        for (int i = 0; i < 2; i++) {
            int idx = t + i * 256, row = idx >> 2, seg = idx & 3;
            cpa16(sws + row * 80 + seg * 16,
                  d_wproj + (size_t)(o0 + row) * C + k0 + seg * 8);
        }
        CP_COMMIT();
        CP_WAIT(0);
        __syncthreads();
#pragma unroll
        for (int kt = 0; kt < 2; kt++) {
            uint32_t a0, a1, a2, a3;
            ldsm4(aW + kt * 32, a0, a1, a2, a3);
#pragma unroll
            for (int nbk = 0; nbk < 4; nbk++) {
                uint32_t b0, b1, b2, b3;
                ldsm4(shs + (nbk * 16 + bHrow) * 80 + kt * 32 + bHcol, b0, b1, b2, b3);
                mma_bf16(acc[nbk][0][0], acc[nbk][0][1], acc[nbk][0][2], acc[nbk][0][3],
                         a0, a1, a2, a3, b0, b1);
                mma_bf16(acc[nbk][1][0], acc[nbk][1][1], acc[nbk][1][2], acc[nbk][1][3],
                         a0, a1, a2, a3, b2, b3);
            }
        }
        __syncthreads();
    }

    const int r = qb + (lane >> 2);
    const float bi0 = bias[o0 + r], bi1 = bias[o0 + r + 8];
    size_t row0 = ((size_t)b * C + o0 + r) * Nn + n0;
    size_t row1 = ((size_t)b * C + o0 + r + 8) * Nn + n0;
#pragma unroll
    for (int nbk = 0; nbk < 4; nbk++)
#pragma unroll
        for (int nn = 0; nn < 2; nn++) {
            int n = nbk * 16 + nn * 8 + 2 * (lane & 3);
            float2 x0 = *(const float2*)&x[row0 + n];
            float2 x1 = *(const float2*)&x[row1 + n];
            *(float2*)&out[row0 + n] = make_float2(x0.x + acc[nbk][nn][0] + bi0,
                                                   x0.y + acc[nbk][nn][1] + bi0);
            *(float2*)&out[row1 + n] = make_float2(x1.x + acc[nbk][nn][2] + bi1,
                                                   x1.y + acc[nbk][nn][3] + bi1);
        }
}

// ---------------------------------------------------------------------------
extern "C" void kernel_launch(void* const* d_in, const int* in_sizes, int n_in,
                              void* d_out, int out_size) {
    const float* x  = (const float*)d_in[0];
    const float* nw = (const float*)d_in[1];
    const float* nb = (const float*)d_in[2];
    const float* qw = (const float*)d_in[3];
    const float* qb = (const float*)d_in[4];
    const float* pw = (const float*)d_in[5];
    const float* pb = (const float*)d_in[6];
    float* out = (float*)d_out;

    cudaFuncSetAttribute(flash_mma, cudaFuncAttributeMaxDynamicSharedMemorySize,
                         SMEM_FLASH);
    cudaFuncSetAttribute(qkv_mma, cudaFuncAttributeMaxDynamicSharedMemorySize,
                         SMEM_QKV);

    wconv<<<256, 256>>>(qw, pw);
    gn_stats<<<Bb * G, 256>>>(x, nw, nb);
    qkv_mma<<<dim3(Nn / 64, 1, Bb), 256, SMEM_QKV>>>(x, qb);
    flash_mma<<<dim3(Nn / TQ, Bb), 256, SMEM_FLASH>>>();
    proj_mma<<<dim3(Nn / 64, C / 128, Bb), 256>>>(x, pb, out);
}

// round 17
// speedup vs baseline: 1.1578x; 1.0015x over previous
#include <cuda_runtime.h>
#include <cuda_bf16.h>
#include <stdint.h>
#include <cstdint>
#include <math.h>

#define Bb 2
#define C 256
#define Nn 8192
#define G 32
#define CPG 8
#define TQ 128
#define TK 64
#define NT (Nn / TK)   // 128 key tiles

// Scratch (no allocations allowed)
__device__ __nv_bfloat16 d_q[(size_t)Bb * Nn * C];     // [b][n][c]
__device__ __nv_bfloat16 d_k[(size_t)Bb * Nn * C];     // [b][n][c]
__device__ __nv_bfloat16 d_v[(size_t)Bb * C * Nn];     // [b][c][n]
__device__ __nv_bfloat16 d_attno[(size_t)Bb * Nn * C]; // [b][n][c] bf16
__device__ __nv_bfloat16 d_wqkv[768 * C];              // bf16 qkv weights
__device__ __nv_bfloat16 d_wproj[C * C];               // bf16 proj weights
__device__ float d_ga[Bb * C];
__device__ float d_gb[Bb * C];

// ---------------------------------------------------------------------------
__device__ __forceinline__ uint32_t smem_u32(const void* p) {
    uint32_t a;
    asm("{ .reg .u64 t; cvta.to.shared.u64 t, %1; cvt.u32.u64 %0, t; }" : "=r"(a) : "l"(p));
    return a;
}
__device__ __forceinline__ void ldsm4(uint32_t a, uint32_t& d0, uint32_t& d1,
                                      uint32_t& d2, uint32_t& d3) {
    asm volatile("ldmatrix.sync.aligned.m8n8.x4.shared.b16 {%0,%1,%2,%3}, [%4];"
                 : "=r"(d0), "=r"(d1), "=r"(d2), "=r"(d3) : "r"(a));
}
__device__ __forceinline__ void mma_bf16(float& c0, float& c1, float& c2, float& c3,
                                         uint32_t a0, uint32_t a1, uint32_t a2, uint32_t a3,
                                         uint32_t b0, uint32_t b1) {
    asm volatile("mma.sync.aligned.m16n8k16.row.col.f32.bf16.bf16.f32 "
                 "{%0,%1,%2,%3}, {%4,%5,%6,%7}, {%8,%9}, {%0,%1,%2,%3};"
                 : "+f"(c0), "+f"(c1), "+f"(c2), "+f"(c3)
                 : "r"(a0), "r"(a1), "r"(a2), "r"(a3), "r"(b0), "r"(b1));
}
__device__ __forceinline__ void cpa16(uint32_t dst, const void* src) {
    asm volatile("cp.async.cg.shared.global [%0], [%1], 16;" :: "r"(dst), "l"(src) : "memory");
}
#define CP_COMMIT() asm volatile("cp.async.commit_group;" ::: "memory")
#define CP_WAIT(n)  asm volatile("cp.async.wait_group %0;" :: "n"(n) : "memory")

__device__ __forceinline__ uint32_t packbf2(float a, float b) {
    __nv_bfloat162 h = __float22bfloat162_rn(make_float2(a, b));
    return *(uint32_t*)&h;
}
__device__ __forceinline__ uint32_t packu16(uint32_t lo, uint32_t hi) {
    return (lo & 0xffffu) | (hi << 16);
}

// ---------------------------------------------------------------------------
// Kernel 0: W fp32 -> bf16 pre-convert (qkv 768x256 then proj 256x256)
// ---------------------------------------------------------------------------
__global__ __launch_bounds__(256) void wconv(const float* __restrict__ qw,
                                             const float* __restrict__ pw) {
    int idx = blockIdx.x * 256 + threadIdx.x;   // group of 4 elems
    if (idx < 49152) {
        float4 v4 = *(const float4*)&qw[(size_t)idx * 4];
        uint32_t* dp = (uint32_t*)&d_wqkv[(size_t)idx * 4];
        dp[0] = packbf2(v4.x, v4.y);
        dp[1] = packbf2(v4.z, v4.w);
    } else {
        int j = idx - 49152;
        float4 v4 = *(const float4*)&pw[(size_t)j * 4];
        uint32_t* dp = (uint32_t*)&d_wproj[(size_t)j * 4];
        dp[0] = packbf2(v4.x, v4.y);
        dp[1] = packbf2(v4.z, v4.w);
    }
}

// ---------------------------------------------------------------------------
// Kernel 1: GroupNorm statistics -> per-channel affine params
// ---------------------------------------------------------------------------
__global__ __launch_bounds__(256) void gn_stats(const float* __restrict__ x,
                                                const float* __restrict__ nw,
                                                const float* __restrict__ nb) {
    int b = blockIdx.x >> 5, g = blockIdx.x & 31;
    const float4* p = (const float4*)(x + ((size_t)b * C + (size_t)g * CPG) * Nn);
    float s = 0.f, ss = 0.f;
    const int total4 = CPG * Nn / 4;
    for (int i = threadIdx.x; i < total4; i += 256) {
        float4 v4 = p[i];
        s += v4.x + v4.y + v4.z + v4.w;
        ss += v4.x * v4.x + v4.y * v4.y + v4.z * v4.z + v4.w * v4.w;
    }
    for (int off = 16; off; off >>= 1) {
        s += __shfl_xor_sync(0xffffffffu, s, off);
        ss += __shfl_xor_sync(0xffffffffu, ss, off);
    }
    __shared__ float rsm[8], rssm[8];
    int w = threadIdx.x >> 5, ln = threadIdx.x & 31;
    if (ln == 0) { rsm[w] = s; rssm[w] = ss; }
    __syncthreads();
    if (threadIdx.x < 8) {
        s = rsm[threadIdx.x]; ss = rssm[threadIdx.x];
        for (int off = 4; off; off >>= 1) {
            s += __shfl_xor_sync(0xffu, s, off);
            ss += __shfl_xor_sync(0xffu, ss, off);
        }
        float mean = s * (1.f / 65536.f);
        float var = ss * (1.f / 65536.f) - mean * mean;
        float rstd = rsqrtf(var + 1e-5f);
        int c = g * CPG + threadIdx.x;
        float wv = nw[c];
        d_ga[b * C + c] = rstd * wv;
        d_gb[b * C + c] = nb[c] - mean * rstd * wv;
    }
}

// ---------------------------------------------------------------------------
// Kernel 2: QKV GEMM, single pass over x, cp.async double-buffered W (bf16).
// ---------------------------------------------------------------------------
#define QH_OFF 0u
#define QW_OFF 33792u
#define QC_OFF 74752u
#define SMEM_QKV 93184

__global__ __launch_bounds__(256) void qkv_mma(const float* __restrict__ x,
                                               const float* __restrict__ bias) {
    extern __shared__ __align__(16) char qsm[];
    char* hs_ = qsm + QH_OFF;
    char* sc_ = qsm + QC_OFF;
    const uint32_t shs = smem_u32(hs_);
    const uint32_t sw0 = shs + QW_OFF;
    const int b = blockIdx.z, n0 = blockIdx.x * 64;
    const int t = threadIdx.x, w = t >> 5, lane = t & 31;
    const float* xb = x + (size_t)b * C * Nn;

    for (int k0 = 0; k0 < C; k0 += 32) {
#pragma unroll
        for (int i = 0; i < 2; i++) {
            int idx = t + i * 256, cc = idx >> 4, n4 = idx & 15;
            int c = k0 + cc;
            float av = d_ga[b * C + c], bv = d_gb[b * C + c];
            float4 v4 = *(const float4*)&xb[(size_t)c * Nn + n0 + n4 * 4];
            *(float4*)(sc_ + (cc * 68 + n4 * 4) * 4) =
                make_float4(v4.x * av + bv, v4.y * av + bv, v4.z * av + bv, v4.w * av + bv);
        }
        __syncthreads();
        {
            int n = t & 63, kg = t >> 6;
            float f[8];
#pragma unroll
            for (int j = 0; j < 8; j++)
                f[j] = *(float*)(sc_ + ((kg * 8 + j) * 68 + n) * 4);
            uint4 u;
            u.x = packbf2(f[0], f[1]); u.y = packbf2(f[2], f[3]);
            u.z = packbf2(f[4], f[5]); u.w = packbf2(f[6], f[7]);
            *(uint4*)(hs_ + n * 528 + k0 * 2 + kg * 16) = u;
        }
        __syncthreads();
    }

    const int qb = w * 16;
    const uint32_t bHrow = (lane & 7) + ((lane >> 4) << 3);
    const uint32_t bHcol = (lane & 8) ? 16u : 0u;
    const int r = qb + (lane >> 2);
    const uint32_t aWl = (qb + (lane & 15)) * 80 + ((lane >> 4) << 4);

    for (int s = 0; s < 3; s++) {
        const __nv_bfloat16* Wb = d_wqkv + (size_t)s * 256 * C;
        float acc[2][4][2][4] = {};

#pragma unroll
        for (int i = 0; i < 4; i++) {
            int idx = t + i * 256, row = idx >> 2, seg = idx & 3;
            cpa16(sw0 + row * 80 + seg * 16, Wb + (size_t)row * C + seg * 8);
        }
        CP_COMMIT();

        for (int kc = 0; kc < 8; kc++) {
            const uint32_t wcur = sw0 + (kc & 1) * 20480;
            if (kc < 7) {
                const uint32_t wn = sw0 + ((kc + 1) & 1) * 20480;
                const int k1 = (kc + 1) * 32;
#pragma unroll
                for (int i = 0; i < 4; i++) {
                    int idx = t + i * 256, row = idx >> 2, seg = idx & 3;
                    cpa16(wn + row * 80 + seg * 16, Wb + (size_t)row * C + k1 + seg * 8);
                }
                CP_COMMIT();
                CP_WAIT(1);
            } else {
                CP_WAIT(0);
            }
            __syncthreads();
#pragma unroll
            for (int kt = 0; kt < 2; kt++) {
                uint32_t a0, a1, a2, a3, c0, c1, c2, c3;
                ldsm4(wcur + aWl + kt * 32, a0, a1, a2, a3);
                ldsm4(wcur + aWl + 128 * 80 + kt * 32, c0, c1, c2, c3);
#pragma unroll
                for (int nbk = 0; nbk < 4; nbk++) {
                    uint32_t b0, b1, b2, b3;
                    ldsm4(shs + (nbk * 16 + bHrow) * 528 + kc * 64 + kt * 32 + bHcol,
                          b0, b1, b2, b3);
                    mma_bf16(acc[0][nbk][0][0], acc[0][nbk][0][1], acc[0][nbk][0][2], acc[0][nbk][0][3],
                             a0, a1, a2, a3, b0, b1);
                    mma_bf16(acc[0][nbk][1][0], acc[0][nbk][1][1], acc[0][nbk][1][2], acc[0][nbk][1][3],
                             a0, a1, a2, a3, b2, b3);
                    mma_bf16(acc[1][nbk][0][0], acc[1][nbk][0][1], acc[1][nbk][0][2], acc[1][nbk][0][3],
                             c0, c1, c2, c3, b0, b1);
                    mma_bf16(acc[1][nbk][1][0], acc[1][nbk][1][1], acc[1][nbk][1][2], acc[1][nbk][1][3],
                             c0, c1, c2, c3, b2, b3);
                }
            }
            __syncthreads();
        }

        if (s < 2) {
            __nv_bfloat16* dst = ((s == 0) ? d_q : d_k) + (size_t)b * Nn * C;
#pragma unroll
            for (int h = 0; h < 2; h++) {
                float bi0 = bias[s * 256 + h * 128 + r];
                float bi1 = bias[s * 256 + h * 128 + r + 8];
#pragma unroll
                for (int nbk = 0; nbk < 4; nbk++)
#pragma unroll
                    for (int nn = 0; nn < 2; nn++) {
                        int n = nbk * 16 + nn * 8 + 2 * (lane & 3);
                        *(uint32_t*)(sc_ + r * 144 + n * 2) =
                            packbf2(acc[h][nbk][nn][0] + bi0, acc[h][nbk][nn][1] + bi0);
                        *(uint32_t*)(sc_ + (r + 8) * 144 + n * 2) =
                            packbf2(acc[h][nbk][nn][2] + bi1, acc[h][nbk][nn][3] + bi1);
                    }
                __syncthreads();
#pragma unroll
                for (int i = 0; i < 4; i++) {
                    int idx = t + i * 256, n = idx & 63, og = idx >> 6;
                    uint32_t hh[8];
#pragma unroll
                    for (int j = 0; j < 8; j++)
                        hh[j] = *(uint16_t*)(sc_ + (og * 8 + j) * 144 + n * 2);
                    uint4 u;
                    u.x = packu16(hh[0], hh[1]); u.y = packu16(hh[2], hh[3]);
                    u.z = packu16(hh[4], hh[5]); u.w = packu16(hh[6], hh[7]);
                    *(uint4*)&dst[(size_t)(n0 + n) * C + h * 128 + og * 8] = u;
                }
                __syncthreads();
            }
        } else {
            __nv_bfloat16* dst = d_v + (size_t)b * C * Nn;
#pragma unroll
            for (int h = 0; h < 2; h++) {
                int ch = h * 128 + r;
                float bi0 = bias[512 + ch], bi1 = bias[512 + ch + 8];
#pragma unroll
                for (int nbk = 0; nbk < 4; nbk++)
#pragma unroll
                    for (int nn = 0; nn < 2; nn++) {
                        int n = n0 + nbk * 16 + nn * 8 + 2 * (lane & 3);
                        *(uint32_t*)&dst[(size_t)ch * Nn + n] =
                            packbf2(acc[h][nbk][nn][0] + bi0, acc[h][nbk][nn][1] + bi0);
                        *(uint32_t*)&dst[(size_t)(ch + 8) * Nn + n] =
                            packbf2(acc[h][nbk][nn][2] + bi1, acc[h][nbk][nn][3] + bi1);
                    }
            }
        }
    }
}

// ---------------------------------------------------------------------------
// Kernel 3: bf16 flash attention, FA2 register-P. TQ=128, TK=64.
// PV loop reordered ka-outer/cb-inner: 32 independent accumulator chains.
// ---------------------------------------------------------------------------
#define QS_OFF  0u
#define KS0_OFF 67584u
#define KS1_OFF 101376u
#define VS0_OFF 135168u
#define VS1_OFF 172032u
#define SMEM_FLASH 208896

__global__ __launch_bounds__(256, 1) void flash_mma() {
    extern __shared__ __align__(16) char sm[];
    const uint32_t sb = smem_u32(sm);
    const int t = threadIdx.x, w = t >> 5, lane = t & 31;
    const int b = blockIdx.y, q0 = blockIdx.x * TQ;
    const __nv_bfloat16* qg = d_q + (size_t)b * Nn * C;
    const __nv_bfloat16* kg = d_k + (size_t)b * Nn * C;
    const __nv_bfloat16* vg = d_v + (size_t)b * C * Nn;

#pragma unroll
    for (int i = 0; i < 16; i++) {
        int g = t + i * 256, row = g >> 5, ck = g & 31;
        cpa16(sb + QS_OFF + row * 528 + ck * 16, qg + (size_t)(q0 + row) * C + ck * 8);
    }
    CP_COMMIT();
#pragma unroll
    for (int i = 0; i < 8; i++) {
        int g = t + i * 256, row = g >> 5, ck = g & 31;
        cpa16(sb + KS0_OFF + row * 528 + ck * 16, kg + (size_t)row * C + ck * 8);
    }
#pragma unroll
    for (int i = 0; i < 8; i++) {
        int g = t + i * 256, ch = g >> 3, ck = g & 7;
        cpa16(sb + VS0_OFF + ch * 144 + ck * 16, vg + (size_t)ch * Nn + ck * 8);
    }
    CP_COMMIT();

    float O[32][4];
#pragma unroll
    for (int m = 0; m < 32; m++)
#pragma unroll
        for (int c = 0; c < 4; c++) O[m][c] = 0.f;
    float l0 = 0.f, l1 = 0.f;

    const int qb = w * 16;
    const uint32_t aQ = sb + QS_OFF + (qb + (lane & 15)) * 528 + ((lane >> 4) * 8) * 2;
    const uint32_t bKrow = (lane & 7) + ((lane >> 4) << 3);
    const uint32_t bKcol = (lane & 8) ? 16u : 0u;

    for (int tile = 0; tile < NT; tile++) {
        const uint32_t kcur = sb + ((tile & 1) ? KS1_OFF : KS0_OFF);
        const uint32_t vcur = sb + ((tile & 1) ? VS1_OFF : VS0_OFF);
        if (tile + 1 < NT) {
            const uint32_t kn = sb + (((tile + 1) & 1) ? KS1_OFF : KS0_OFF);
            const uint32_t vn = sb + (((tile + 1) & 1) ? VS1_OFF : VS0_OFF);
            const int kk1 = (tile + 1) * TK;
#pragma unroll
            for (int i = 0; i < 8; i++) {
                int g = t + i * 256, row = g >> 5, ck = g & 31;
                cpa16(kn + row * 528 + ck * 16, kg + (size_t)(kk1 + row) * C + ck * 8);
            }
#pragma unroll
            for (int i = 0; i < 8; i++) {
                int g = t + i * 256, ch = g >> 3, ck = g & 7;
                cpa16(vn + ch * 144 + ck * 16, vg + (size_t)ch * Nn + kk1 + ck * 8);
            }
            CP_COMMIT();
            CP_WAIT(1);
        } else {
            CP_WAIT(0);
        }
        __syncthreads();

        // ---- S = Q K^T ----
        float S[8][4];
#pragma unroll
        for (int nt = 0; nt < 8; nt++)
#pragma unroll
            for (int c = 0; c < 4; c++) S[nt][c] = 0.f;
#pragma unroll
        for (int kt = 0; kt < 16; kt++) {
            uint32_t a0, a1, a2, a3;
            ldsm4(aQ + kt * 32, a0, a1, a2, a3);
#pragma unroll
            for (int kb = 0; kb < 4; kb++) {
                uint32_t b0, b1, b2, b3;
                ldsm4(kcur + (kb * 16 + bKrow) * 528 + kt * 32 + bKcol, b0, b1, b2, b3);
                mma_bf16(S[2 * kb][0], S[2 * kb][1], S[2 * kb][2], S[2 * kb][3],
                         a0, a1, a2, a3, b0, b1);
                mma_bf16(S[2 * kb + 1][0], S[2 * kb + 1][1], S[2 * kb + 1][2], S[2 * kb + 1][3],
                         a0, a1, a2, a3, b2, b3);
            }
        }

        // ---- softmax (no max) -> A-fragments in registers ----
        uint32_t aP[4][4];
#pragma unroll
        for (int ka = 0; ka < 4; ka++) {
            float p00 = __expf(S[2 * ka][0] * 0.0625f);
            float p01 = __expf(S[2 * ka][1] * 0.0625f);
            float p02 = __expf(S[2 * ka][2] * 0.0625f);
            float p03 = __expf(S[2 * ka][3] * 0.0625f);
            float p10 = __expf(S[2 * ka + 1][0] * 0.0625f);
            float p11 = __expf(S[2 * ka + 1][1] * 0.0625f);
            float p12 = __expf(S[2 * ka + 1][2] * 0.0625f);
            float p13 = __expf(S[2 * ka + 1][3] * 0.0625f);
            l0 += (p00 + p01) + (p10 + p11);
            l1 += (p02 + p03) + (p12 + p13);
            aP[ka][0] = packbf2(p00, p01);
            aP[ka][1] = packbf2(p02, p03);
            aP[ka][2] = packbf2(p10, p11);
            aP[ka][3] = packbf2(p12, p13);
        }

        // ---- O += P V^T : ka outer, cb inner -> 32 independent chains ----
#pragma unroll
        for (int ka = 0; ka < 4; ka++) {
#pragma unroll
            for (int cb = 0; cb < 16; cb++) {
                uint32_t b0, b1, b2, b3;
                ldsm4(vcur + (cb * 16 + bKrow) * 144 + bKcol + ka * 32, b0, b1, b2, b3);
                mma_bf16(O[2 * cb][0], O[2 * cb][1], O[2 * cb][2], O[2 * cb][3],
                         aP[ka][0], aP[ka][1], aP[ka][2], aP[ka][3], b0, b1);
                mma_bf16(O[2 * cb + 1][0], O[2 * cb + 1][1], O[2 * cb + 1][2], O[2 * cb + 1][3],
                         aP[ka][0], aP[ka][1], aP[ka][2], aP[ka][3], b2, b3);
            }
        }
        __syncthreads();
    }

    // ---- reduce l across quad, normalize, store [n][c] ----
    l0 += __shfl_xor_sync(0xffffffffu, l0, 1);
    l0 += __shfl_xor_sync(0xffffffffu, l0, 2);
    l1 += __shfl_xor_sync(0xffffffffu, l1, 1);
    l1 += __shfl_xor_sync(0xffffffffu, l1, 2);
    float inv0 = 1.f / l0, inv1 = 1.f / l1;
    __nv_bfloat16* ao = d_attno + (size_t)b * Nn * C;
    int nr = q0 + qb + (lane >> 2);
#pragma unroll
    for (int ob = 0; ob < 32; ob++) {
        int cc = (ob >> 1) * 16 + (ob & 1) * 8 + 2 * (lane & 3);
        *(uint32_t*)&ao[(size_t)nr * C + cc] = packbf2(O[ob][0] * inv0, O[ob][1] * inv0);
        *(uint32_t*)&ao[(size_t)(nr + 8) * C + cc] = packbf2(O[ob][2] * inv1, O[ob][3] * inv1);
    }
}

// ---------------------------------------------------------------------------
// Kernel 4: projection GEMM + bias + residual; W from pre-converted bf16.
// ---------------------------------------------------------------------------
__global__ __launch_bounds__(256) void proj_mma(const float* __restrict__ x,
                                                const float* __restrict__ bias,
                                                float* __restrict__ out) {
    __shared__ __align__(16) char ws_[128 * 80];
    __shared__ __align__(16) char hs_[64 * 80];
    const uint32_t sws = smem_u32(ws_), shs = smem_u32(hs_);
    const int b = blockIdx.z, o0 = blockIdx.y * 128, n0 = blockIdx.x * 64;
    const int t = threadIdx.x, w = t >> 5, lane = t & 31;
    const __nv_bfloat16* ab = d_attno + (size_t)b * Nn * C;

    const int qb = w * 16;
    const uint32_t aW = sws + (qb + (lane & 15)) * 80 + ((lane >> 4) << 4);
    const uint32_t bHrow = (lane & 7) + ((lane >> 4) << 3);
    const uint32_t bHcol = (lane & 8) ? 16u : 0u;

    float acc[4][2][4] = {};

    for (int k0 = 0; k0 < C; k0 += 32) {
        {
            int nn = t >> 2, ck = t & 3;
            cpa16(shs + nn * 80 + ck * 16, ab + (size_t)(n0 + nn) * C + k0 + ck * 8);
        }
#pragma unroll
        for (int i = 0; i < 2; i++) {
            int idx = t + i * 256, row = idx >> 2, seg = idx & 3;
            cpa16(sws + row * 80 + seg * 16,
                  d_wproj + (size_t)(o0 + row) * C + k0 + seg * 8);
        }
        CP_COMMIT();
        CP_WAIT(0);
        __syncthreads();
#pragma unroll
        for (int kt = 0; kt < 2; kt++) {
            uint32_t a0, a1, a2, a3;
            ldsm4(aW + kt * 32, a0, a1, a2, a3);
#pragma unroll
            for (int nbk = 0; nbk < 4; nbk++) {
                uint32_t b0, b1, b2, b3;
                ldsm4(shs + (nbk * 16 + bHrow) * 80 + kt * 32 + bHcol, b0, b1, b2, b3);
                mma_bf16(acc[nbk][0][0], acc[nbk][0][1], acc[nbk][0][2], acc[nbk][0][3],
                         a0, a1, a2, a3, b0, b1);
                mma_bf16(acc[nbk][1][0], acc[nbk][1][1], acc[nbk][1][2], acc[nbk][1][3],
                         a0, a1, a2, a3, b2, b3);
            }
        }
        __syncthreads();
    }

    const int r = qb + (lane >> 2);
    const float bi0 = bias[o0 + r], bi1 = bias[o0 + r + 8];
    size_t row0 = ((size_t)b * C + o0 + r) * Nn + n0;
    size_t row1 = ((size_t)b * C + o0 + r + 8) * Nn + n0;
#pragma unroll
    for (int nbk = 0; nbk < 4; nbk++)
#pragma unroll
        for (int nn = 0; nn < 2; nn++) {
            int n = nbk * 16 + nn * 8 + 2 * (lane & 3);
            float2 x0 = *(const float2*)&x[row0 + n];
            float2 x1 = *(const float2*)&x[row1 + n];
            *(float2*)&out[row0 + n] = make_float2(x0.x + acc[nbk][nn][0] + bi0,
                                                   x0.y + acc[nbk][nn][1] + bi0);
            *(float2*)&out[row1 + n] = make_float2(x1.x + acc[nbk][nn][2] + bi1,
                                                   x1.y + acc[nbk][nn][3] + bi1);
        }
}

// ---------------------------------------------------------------------------
extern "C" void kernel_launch(void* const* d_in, const int* in_sizes, int n_in,
                              void* d_out, int out_size) {
    const float* x  = (const float*)d_in[0];
    const float* nw = (const float*)d_in[1];
    const float* nb = (const float*)d_in[2];
    const float* qw = (const float*)d_in[3];
    const float* qb = (const float*)d_in[4];
    const float* pw = (const float*)d_in[5];
    const float* pb = (const float*)d_in[6];
    float* out = (float*)d_out;

    cudaFuncSetAttribute(flash_mma, cudaFuncAttributeMaxDynamicSharedMemorySize,
                         SMEM_FLASH);
    cudaFuncSetAttribute(qkv_mma, cudaFuncAttributeMaxDynamicSharedMemorySize,
                         SMEM_QKV);

    wconv<<<256, 256>>>(qw, pw);
    gn_stats<<<Bb * G, 256>>>(x, nw, nb);
    qkv_mma<<<dim3(Nn / 64, 1, Bb), 256, SMEM_QKV>>>(x, qb);
    flash_mma<<<dim3(Nn / TQ, Bb), 256, SMEM_FLASH>>>();
    proj_mma<<<dim3(Nn / 64, C / 128, Bb), 256>>>(x, pb, out);
}